// round 2
// baseline (speedup 1.0000x reference)
#include <cuda_runtime.h>

// ---------------------------------------------------------------------------
// EquivDiffusion: hypergraph two-stage MLP diffusion.
// Algebraic restructuring:
//   Y1 = MLP1(x)                    (on N rows, not M)
//   Xe = scatter_mean(Y1[vertex], edges)
//   P  = x  @ W2a   (first half of w2_1)
//   Q  = Xe @ W2b   (second half of w2_1)
//   per-incidence: h = relu(LN(P[v] + Q[e] + b2_1))   -> scatter_mean over v
//   out = (1-a) * mask(cnt>0) * (Smean @ w2_2 + b2_2) + a * x
// ---------------------------------------------------------------------------

namespace {
constexpr int   kN = 40000;
constexpr int   kE = 20000;
constexpr int   kM = 640000;
constexpr int   kD = 128;
constexpr float kAlpha = 0.1f;
constexpr float kEps   = 1e-5f;
}

// Scratch (static device arrays: allocation-free per harness rules)
__device__ __align__(16) float g_T1[kN * kD];
__device__ __align__(16) float g_Y1[kN * kD];
__device__ __align__(16) float g_P [kN * kD];
__device__ __align__(16) float g_S [kN * kD];
__device__ __align__(16) float g_Xe[kE * kD];
__device__ __align__(16) float g_Q [kE * kD];
__device__ float g_ecnt[kE];
__device__ float g_vcnt[kN];
__device__ int   g_vi[kM];
__device__ int   g_ej[kM];
__device__ int   g_is64;

// ---------------------------------------------------------------------------
// red.global.add.v4.f32 (sm_90+): vector atomic without return.
// ---------------------------------------------------------------------------
__device__ __forceinline__ void red_add_f32x4(float* addr, float4 v)
{
    asm volatile("red.global.add.v4.f32 [%0], {%1, %2, %3, %4};"
                 :: "l"(addr), "f"(v.x), "f"(v.y), "f"(v.z), "f"(v.w)
                 : "memory");
}

// ---------------------------------------------------------------------------
// Probe: decide whether edge_index is int64 or int32.
// For int64 data (values < 2^31), every high 32-bit word is zero.
// ---------------------------------------------------------------------------
__global__ void probe_kernel(const int* __restrict__ ei_as_i32)
{
    if (threadIdx.x != 0 || blockIdx.x != 0) return;
    int all_zero_high = 1;
    // sample 128 chunks spread over both halves (as-if-int64 layout)
    for (int k = 0; k < 128; k++) {
        const int idx = k * (kM / 64);                 // spreads over 2*M ints
        if (ei_as_i32[2 * idx + 1] != 0) { all_zero_high = 0; break; }
    }
    g_is64 = all_zero_high;
}

// ---------------------------------------------------------------------------
// Decode indices into flat int arrays (works for both int32/int64 storage).
// ---------------------------------------------------------------------------
__global__ __launch_bounds__(256)
void decode_kernel(const void* __restrict__ ei)
{
    const int t = blockIdx.x * blockDim.x + threadIdx.x;
    if (t >= kM) return;
    if (g_is64) {
        const long long* p = (const long long*)ei;
        g_vi[t] = (int)p[t];
        g_ej[t] = (int)p[kM + t];
    } else {
        const int* p = (const int*)ei;
        g_vi[t] = p[t];
        g_ej[t] = p[kM + t];
    }
}

// ---------------------------------------------------------------------------
__global__ void zero_kernel()
{
    const int stride = gridDim.x * blockDim.x;
    const int t = blockIdx.x * blockDim.x + threadIdx.x;
    for (int i = t; i < kE * kD; i += stride) g_Xe[i] = 0.f;
    for (int i = t; i < kN * kD; i += stride) g_S[i]  = 0.f;
    for (int i = t; i < kE;      i += stride) g_ecnt[i] = 0.f;
    for (int i = t; i < kN;      i += stride) g_vcnt[i] = 0.f;
}

// ---------------------------------------------------------------------------
// 128x128 block-tiled GEMM, C[rows,128] = A[rows,128] @ B[128,128] (+ epilogue)
// 256 threads, 8x8 per-thread register tile.
// ---------------------------------------------------------------------------
enum { EPI_PLAIN = 0, EPI_LNRELU = 1, EPI_FINAL = 2 };

template <int EPI>
__global__ __launch_bounds__(256)
void gemm128_kernel(const float* __restrict__ A, const float* __restrict__ B,
                    const float* __restrict__ bias,
                    const float* __restrict__ gamma, const float* __restrict__ beta,
                    const float* __restrict__ x0, const float* __restrict__ cnt,
                    float* __restrict__ C, int rows)
{
    __shared__ float As[8][132];   // [k][row], padded (528B row stride, 16B-aligned)
    __shared__ float Bs[8][128];   // [k][col]

    const int tid = threadIdx.x;
    const int tx = tid & 15;       // column group: cols tx*8 .. tx*8+7
    const int ty = tid >> 4;       // row group:    rows ty*8 .. ty*8+7
    const int row0 = blockIdx.x * 128;

    float acc[8][8];
#pragma unroll
    for (int i = 0; i < 8; i++)
#pragma unroll
        for (int j = 0; j < 8; j++) acc[i][j] = 0.f;

    const int lrow = tid >> 1;
    const int lk4  = (tid & 1) * 4;
    const int bk   = tid >> 5;
    const int bn   = (tid & 31) * 4;
    const int arow = row0 + lrow;
    const bool aval = (arow < rows);
    const float* Aptr = A + (size_t)arow * kD + lk4;

    for (int kk = 0; kk < kD; kk += 8) {
        float4 av = make_float4(0.f, 0.f, 0.f, 0.f);
        if (aval) av = *(const float4*)(Aptr + kk);
        As[lk4 + 0][lrow] = av.x;
        As[lk4 + 1][lrow] = av.y;
        As[lk4 + 2][lrow] = av.z;
        As[lk4 + 3][lrow] = av.w;
        *(float4*)&Bs[bk][bn] = *(const float4*)(B + (size_t)(kk + bk) * kD + bn);
        __syncthreads();
#pragma unroll
        for (int k = 0; k < 8; k++) {
            float a[8], b[8];
            *(float4*)(a)     = *(const float4*)&As[k][ty * 8];
            *(float4*)(a + 4) = *(const float4*)&As[k][ty * 8 + 4];
            *(float4*)(b)     = *(const float4*)&Bs[k][tx * 8];
            *(float4*)(b + 4) = *(const float4*)&Bs[k][tx * 8 + 4];
#pragma unroll
            for (int i = 0; i < 8; i++)
#pragma unroll
                for (int j = 0; j < 8; j++)
                    acc[i][j] = fmaf(a[i], b[j], acc[i][j]);
        }
        __syncthreads();
    }

    // bias (columns tx*8 .. tx*8+7)
    if (bias != nullptr) {
        float bv[8];
        *(float4*)(bv)     = *(const float4*)(bias + tx * 8);
        *(float4*)(bv + 4) = *(const float4*)(bias + tx * 8 + 4);
#pragma unroll
        for (int i = 0; i < 8; i++)
#pragma unroll
            for (int j = 0; j < 8; j++) acc[i][j] += bv[j];
    }

    if (EPI == EPI_LNRELU) {
        float gm[8], bt[8];
        *(float4*)(gm)     = *(const float4*)(gamma + tx * 8);
        *(float4*)(gm + 4) = *(const float4*)(gamma + tx * 8 + 4);
        *(float4*)(bt)     = *(const float4*)(beta + tx * 8);
        *(float4*)(bt + 4) = *(const float4*)(beta + tx * 8 + 4);
#pragma unroll
        for (int i = 0; i < 8; i++) {
            float s = 0.f, s2 = 0.f;
#pragma unroll
            for (int j = 0; j < 8; j++) { float h = acc[i][j]; s += h; s2 += h * h; }
            // reduce across the 16 threads (same ty) holding this row
#pragma unroll
            for (int o = 8; o >= 1; o >>= 1) {
                s  += __shfl_xor_sync(0xffffffffu, s,  o);
                s2 += __shfl_xor_sync(0xffffffffu, s2, o);
            }
            const float mu   = s * (1.f / 128.f);
            const float var  = s2 * (1.f / 128.f) - mu * mu;
            const float rstd = rsqrtf(var + kEps);
#pragma unroll
            for (int j = 0; j < 8; j++) {
                float v = (acc[i][j] - mu) * rstd * gm[j] + bt[j];
                acc[i][j] = fmaxf(v, 0.f);
            }
        }
    }

#pragma unroll
    for (int i = 0; i < 8; i++) {
        const int r = row0 + ty * 8 + i;
        if (r >= rows) continue;
        float outv[8];
        if (EPI == EPI_FINAL) {
            const float keep = (cnt[r] > 0.f) ? (1.f - kAlpha) : 0.f;
            float xv[8];
            *(float4*)(xv)     = *(const float4*)(x0 + (size_t)r * kD + tx * 8);
            *(float4*)(xv + 4) = *(const float4*)(x0 + (size_t)r * kD + tx * 8 + 4);
#pragma unroll
            for (int j = 0; j < 8; j++)
                outv[j] = keep * acc[i][j] + kAlpha * xv[j];
        } else {
#pragma unroll
            for (int j = 0; j < 8; j++) outv[j] = acc[i][j];
        }
        *(float4*)(C + (size_t)r * kD + tx * 8)     = make_float4(outv[0], outv[1], outv[2], outv[3]);
        *(float4*)(C + (size_t)r * kD + tx * 8 + 4) = make_float4(outv[4], outv[5], outv[6], outv[7]);
    }
}

// ---------------------------------------------------------------------------
// Pass 1: warp per incidence -> atomic accumulate Y1[v] into Xe[e], count edges
// ---------------------------------------------------------------------------
__global__ __launch_bounds__(256)
void scatter_edge_kernel()
{
    const int gw   = (blockIdx.x * blockDim.x + threadIdx.x) >> 5;
    const int lane = threadIdx.x & 31;
    if (gw >= kM) return;
    const int v = g_vi[gw];
    const int e = g_ej[gw];
    const float4 val = *(const float4*)(g_Y1 + (size_t)v * kD + lane * 4);
    red_add_f32x4(g_Xe + (size_t)e * kD + lane * 4, val);
    if (lane == 0) atomicAdd(&g_ecnt[e], 1.0f);
}

// ---------------------------------------------------------------------------
// Row-wise divide by max(cnt,1)
// ---------------------------------------------------------------------------
__global__ __launch_bounds__(256)
void divide_kernel(float* __restrict__ X, const float* __restrict__ cnt, int rows)
{
    const int idx = blockIdx.x * blockDim.x + threadIdx.x;
    if (idx >= rows * 32) return;
    const int r = idx >> 5;
    const float inv = 1.f / fmaxf(cnt[r], 1.f);
    float4* p = (float4*)(X + (size_t)r * kD + (idx & 31) * 4);
    float4 v = *p;
    v.x *= inv; v.y *= inv; v.z *= inv; v.w *= inv;
    *p = v;
}

// ---------------------------------------------------------------------------
// Pass 2: warp per incidence: h = relu(LN(P[v]+Q[e]+b2_1)); scatter into S[v]
// ---------------------------------------------------------------------------
__global__ __launch_bounds__(256)
void inc2_kernel(const float* __restrict__ b1,
                 const float* __restrict__ g,
                 const float* __restrict__ be)
{
    const int gw   = (blockIdx.x * blockDim.x + threadIdx.x) >> 5;
    const int lane = threadIdx.x & 31;
    if (gw >= kM) return;
    const int v = g_vi[gw];
    const int e = g_ej[gw];
    const int c = lane * 4;

    const float4 p  = *(const float4*)(g_P + (size_t)v * kD + c);
    const float4 q  = *(const float4*)(g_Q + (size_t)e * kD + c);
    const float4 bb = *(const float4*)(b1 + c);

    const float h0 = p.x + q.x + bb.x;
    const float h1 = p.y + q.y + bb.y;
    const float h2 = p.z + q.z + bb.z;
    const float h3 = p.w + q.w + bb.w;

    float s  = h0 + h1 + h2 + h3;
    float s2 = h0 * h0 + h1 * h1 + h2 * h2 + h3 * h3;
#pragma unroll
    for (int o = 16; o >= 1; o >>= 1) {
        s  += __shfl_xor_sync(0xffffffffu, s,  o);
        s2 += __shfl_xor_sync(0xffffffffu, s2, o);
    }
    const float mu   = s * (1.f / 128.f);
    const float var  = s2 * (1.f / 128.f) - mu * mu;
    const float rstd = rsqrtf(var + kEps);

    const float4 gg = *(const float4*)(g + c);
    const float4 bt = *(const float4*)(be + c);

    float4 o;
    o.x = fmaxf((h0 - mu) * rstd * gg.x + bt.x, 0.f);
    o.y = fmaxf((h1 - mu) * rstd * gg.y + bt.y, 0.f);
    o.z = fmaxf((h2 - mu) * rstd * gg.z + bt.z, 0.f);
    o.w = fmaxf((h3 - mu) * rstd * gg.w + bt.w, 0.f);

    red_add_f32x4(g_S + (size_t)v * kD + c, o);
    if (lane == 0) atomicAdd(&g_vcnt[v], 1.0f);
}

// ---------------------------------------------------------------------------
extern "C" void kernel_launch(void* const* d_in, const int* in_sizes, int n_in,
                              void* d_out, int out_size)
{
    const float* x    = (const float*)d_in[0];
    const float* w1_1 = (const float*)d_in[1];
    const float* b1_1 = (const float*)d_in[2];
    const float* g1   = (const float*)d_in[3];
    const float* be1  = (const float*)d_in[4];
    const float* w1_2 = (const float*)d_in[5];
    const float* b1_2 = (const float*)d_in[6];
    const float* w2_1 = (const float*)d_in[7];
    const float* b2_1 = (const float*)d_in[8];
    const float* g2   = (const float*)d_in[9];
    const float* be2  = (const float*)d_in[10];
    const float* w2_2 = (const float*)d_in[11];
    const float* b2_2 = (const float*)d_in[12];
    const void*  ei   = d_in[13];
    float* out = (float*)d_out;

    float *T1, *Y1, *P, *S, *Xe, *Q, *ecnt, *vcnt;
    cudaGetSymbolAddress((void**)&T1,   g_T1);
    cudaGetSymbolAddress((void**)&Y1,   g_Y1);
    cudaGetSymbolAddress((void**)&P,    g_P);
    cudaGetSymbolAddress((void**)&S,    g_S);
    cudaGetSymbolAddress((void**)&Xe,   g_Xe);
    cudaGetSymbolAddress((void**)&Q,    g_Q);
    cudaGetSymbolAddress((void**)&ecnt, g_ecnt);
    cudaGetSymbolAddress((void**)&vcnt, g_vcnt);

    const int gbN = (kN + 127) / 128;   // 313
    const int gbE = (kE + 127) / 128;   // 157
    const int incBlocks = kM / 8;       // 80000 (warp per incidence, 8 warps/block)

    // index dtype probe + decode + zero accumulators
    probe_kernel<<<1, 32>>>((const int*)ei);
    decode_kernel<<<(kM + 255) / 256, 256>>>(ei);
    zero_kernel<<<2048, 256>>>();

    // T1 = relu(LN(x @ w1_1 + b1_1))
    gemm128_kernel<EPI_LNRELU><<<gbN, 256>>>(x, w1_1, b1_1, g1, be1,
                                             nullptr, nullptr, T1, kN);
    // Y1 = T1 @ w1_2 + b1_2
    gemm128_kernel<EPI_PLAIN><<<gbN, 256>>>(T1, w1_2, b1_2, nullptr, nullptr,
                                            nullptr, nullptr, Y1, kN);
    // P = x @ W2a   (bias added in inc2)
    gemm128_kernel<EPI_PLAIN><<<gbN, 256>>>(x, w2_1, nullptr, nullptr, nullptr,
                                            nullptr, nullptr, P, kN);
    // Xe_sum += Y1[vertex] per edge; edge counts
    scatter_edge_kernel<<<incBlocks, 256>>>();
    // Xe = Xe_sum / max(cnt,1)
    divide_kernel<<<(kE * 32 + 255) / 256, 256>>>(Xe, ecnt, kE);
    // Q = Xe @ W2b
    gemm128_kernel<EPI_PLAIN><<<gbE, 256>>>(Xe, w2_1 + 128 * 128, nullptr, nullptr,
                                            nullptr, nullptr, nullptr, Q, kE);
    // S += relu(LN(P[v] + Q[e] + b2_1)); vertex counts
    inc2_kernel<<<incBlocks, 256>>>(b2_1, g2, be2);
    // Smean = S / max(cnt,1)
    divide_kernel<<<(kN * 32 + 255) / 256, 256>>>(S, vcnt, kN);
    // out = (1-a)*mask(cnt>0)*(Smean @ w2_2 + b2_2) + a*x
    gemm128_kernel<EPI_FINAL><<<gbN, 256>>>(S, w2_2, b2_2, nullptr, nullptr,
                                            x, vcnt, out, kN);
}

// round 3
// speedup vs baseline: 1.5094x; 1.5094x over previous
#include <cuda_runtime.h>
#include <cstdint>

// ---------------------------------------------------------------------------
// EquivDiffusion: hypergraph two-stage MLP diffusion.
//   Y1 = MLP1(x)                       (N rows, not M)
//   Xe = scatter_mean(Y1[vertex], edges)
//   P  = x  @ W2a ;  Q = Xe @ W2b      (split of w2_1 over the concat)
//   per-incidence: h = relu(LN(P[v]+Q[e]+b2_1)) -> scatter_mean over v
//   out = (1-a)*mask(cnt>0)*(Smean @ w2_2 + b2_2) + a*x
// GEMMs on tensor cores (tf32 mma.sync), scatter-mean divides folded into
// the next GEMM's A-load as a row scale.
// ---------------------------------------------------------------------------

namespace {
constexpr int   kN = 40000;
constexpr int   kE = 20000;
constexpr int   kM = 640000;
constexpr int   kD = 128;
constexpr float kAlpha = 0.1f;
constexpr float kEps   = 1e-5f;
}

__device__ __align__(16) float g_H1[kN * kD];
__device__ __align__(16) float g_Y1[kN * kD];
__device__ __align__(16) float g_P [kN * kD];
__device__ __align__(16) float g_S [kN * kD];
__device__ __align__(16) float g_Xe[kE * kD];
__device__ __align__(16) float g_Q [kE * kD];
__device__ float g_ecnt[kE];
__device__ float g_vcnt[kN];
__device__ int   g_vi[kM];
__device__ int   g_ej[kM];
__device__ int   g_is64;

// ---------------------------------------------------------------------------
__device__ __forceinline__ void red_add_f32x4(float* addr, float4 v)
{
    asm volatile("red.global.add.v4.f32 [%0], {%1, %2, %3, %4};"
                 :: "l"(addr), "f"(v.x), "f"(v.y), "f"(v.z), "f"(v.w)
                 : "memory");
}

__device__ __forceinline__ uint32_t f2tf32(float f)
{
    uint32_t u;
    asm("cvt.rna.tf32.f32 %0, %1;" : "=r"(u) : "f"(f));
    return u;
}

__device__ __forceinline__ void mma_tf32(float* d, const uint32_t* a, const uint32_t* b)
{
    asm volatile(
        "mma.sync.aligned.m16n8k8.row.col.f32.tf32.tf32.f32 "
        "{%0,%1,%2,%3}, {%4,%5,%6,%7}, {%8,%9}, {%0,%1,%2,%3};"
        : "+f"(d[0]), "+f"(d[1]), "+f"(d[2]), "+f"(d[3])
        : "r"(a[0]), "r"(a[1]), "r"(a[2]), "r"(a[3]), "r"(b[0]), "r"(b[1]));
}

// ---------------------------------------------------------------------------
// Probe: int64 vs int32 edge_index (JAX x64-disabled silently yields int32).
// ---------------------------------------------------------------------------
__global__ void probe_kernel(const int* __restrict__ ei_as_i32)
{
    if (threadIdx.x != 0 || blockIdx.x != 0) return;
    int all_zero_high = 1;
    for (int k = 0; k < 128; k++) {
        const int idx = k * (kM / 64);
        if (ei_as_i32[2 * idx + 1] != 0) { all_zero_high = 0; break; }
    }
    g_is64 = all_zero_high;
}

__global__ __launch_bounds__(256)
void decode_kernel(const void* __restrict__ ei)
{
    const int t = blockIdx.x * blockDim.x + threadIdx.x;
    if (t >= kM) return;
    if (g_is64) {
        const long long* p = (const long long*)ei;
        g_vi[t] = (int)p[t];
        g_ej[t] = (int)p[kM + t];
    } else {
        const int* p = (const int*)ei;
        g_vi[t] = p[t];
        g_ej[t] = p[kM + t];
    }
}

__global__ void zero_kernel()
{
    const int stride = gridDim.x * blockDim.x;
    const int t = blockIdx.x * blockDim.x + threadIdx.x;
    for (int i = t; i < kE * kD; i += stride) g_Xe[i] = 0.f;
    for (int i = t; i < kN * kD; i += stride) g_S[i]  = 0.f;
    for (int i = t; i < kE;      i += stride) g_ecnt[i] = 0.f;
    for (int i = t; i < kN;      i += stride) g_vcnt[i] = 0.f;
}

// ---------------------------------------------------------------------------
// tf32 tensor-core GEMM: C[rows,128] = (rowscale ? diag(1/max(sc,1)) : I) * A @ B (+bias)
// Block: 128x128 C tile, 8 warps (4x2), warp tile 32x64, m16n8k8 MMA.
// EPI==1: out = keep(row) * acc + alpha * x0  (keep = cnt>0 ? 1-alpha : 0)
// ---------------------------------------------------------------------------
template <int EPI>
__global__ __launch_bounds__(256)
void gemm_tf32(const float* __restrict__ A, const float* __restrict__ B,
               const float* __restrict__ bias, const float* __restrict__ rowscale,
               const float* __restrict__ x0, float* __restrict__ C, int rows)
{
    __shared__ float As[2][128][20];   // [buf][row][k] stride 20 -> conflict-free frag reads
    __shared__ float Bs[2][16][136];   // [buf][k][col] stride 136 -> conflict-free

    const int t    = threadIdx.x;
    const int lane = t & 31;
    const int wid  = t >> 5;
    const int wr   = wid & 3;          // warp row (4)
    const int wc   = wid >> 2;         // warp col (2)
    const int lr   = lane >> 2;        // 0..7
    const int lc   = lane & 3;         // 0..3
    const int row0 = blockIdx.x * 128;

    // A staging: thread loads row (t>>1), k chunk (t&1)*8 .. +7
    const int arow = row0 + (t >> 1);
    const bool aval = (arow < rows);
    float sc = 1.f;
    if (rowscale != nullptr && aval) sc = 1.f / fmaxf(rowscale[arow], 1.f);
    const float* Ap = A + (size_t)arow * kD + (t & 1) * 8;
    // B staging: thread loads k row (t>>4), cols (t&15)*8 .. +7
    const float* Bp = B + (size_t)(t >> 4) * kD + (t & 15) * 8;

    float acc[2][8][4];
#pragma unroll
    for (int mt = 0; mt < 2; mt++)
#pragma unroll
        for (int nt = 0; nt < 8; nt++)
#pragma unroll
            for (int i = 0; i < 4; i++) acc[mt][nt][i] = 0.f;

    float4 pa0, pa1, pb0, pb1;
    // prologue: stage 0
    if (aval) { pa0 = *(const float4*)Ap; pa1 = *(const float4*)(Ap + 4); }
    else { pa0 = make_float4(0,0,0,0); pa1 = make_float4(0,0,0,0); }
    pb0 = *(const float4*)Bp; pb1 = *(const float4*)(Bp + 4);
    {
        float* as = &As[0][t >> 1][(t & 1) * 8];
        as[0] = pa0.x * sc; as[1] = pa0.y * sc; as[2] = pa0.z * sc; as[3] = pa0.w * sc;
        as[4] = pa1.x * sc; as[5] = pa1.y * sc; as[6] = pa1.z * sc; as[7] = pa1.w * sc;
        *(float4*)&Bs[0][t >> 4][(t & 15) * 8]     = pb0;
        *(float4*)&Bs[0][t >> 4][(t & 15) * 8 + 4] = pb1;
    }
    __syncthreads();

    for (int s = 0; s < 8; s++) {
        const int buf = s & 1;
        if (s < 7) {
            if (aval) {
                const float* ap = Ap + (s + 1) * 16;
                pa0 = *(const float4*)ap; pa1 = *(const float4*)(ap + 4);
            }
            const float* bp = Bp + (size_t)(s + 1) * 16 * kD;
            pb0 = *(const float4*)bp; pb1 = *(const float4*)(bp + 4);
        }
#pragma unroll
        for (int h = 0; h < 2; h++) {
            const int ks = h * 8;
            uint32_t af[2][4];
#pragma unroll
            for (int mt = 0; mt < 2; mt++) {
                const int rb = wr * 32 + mt * 16;
                af[mt][0] = f2tf32(As[buf][rb + lr][ks + lc]);
                af[mt][1] = f2tf32(As[buf][rb + lr + 8][ks + lc]);
                af[mt][2] = f2tf32(As[buf][rb + lr][ks + lc + 4]);
                af[mt][3] = f2tf32(As[buf][rb + lr + 8][ks + lc + 4]);
            }
            uint32_t bfr[8][2];
#pragma unroll
            for (int nt = 0; nt < 8; nt++) {
                const int cb = wc * 64 + nt * 8;
                bfr[nt][0] = f2tf32(Bs[buf][ks + lc][cb + lr]);
                bfr[nt][1] = f2tf32(Bs[buf][ks + lc + 4][cb + lr]);
            }
#pragma unroll
            for (int mt = 0; mt < 2; mt++)
#pragma unroll
                for (int nt = 0; nt < 8; nt++)
                    mma_tf32(acc[mt][nt], af[mt], bfr[nt]);
        }
        if (s < 7) {
            const int nb = buf ^ 1;
            float* as = &As[nb][t >> 1][(t & 1) * 8];
            as[0] = pa0.x * sc; as[1] = pa0.y * sc; as[2] = pa0.z * sc; as[3] = pa0.w * sc;
            as[4] = pa1.x * sc; as[5] = pa1.y * sc; as[6] = pa1.z * sc; as[7] = pa1.w * sc;
            *(float4*)&Bs[nb][t >> 4][(t & 15) * 8]     = pb0;
            *(float4*)&Bs[nb][t >> 4][(t & 15) * 8 + 4] = pb1;
            __syncthreads();
        }
    }

    // Epilogue
#pragma unroll
    for (int mt = 0; mt < 2; mt++) {
        const int r0 = row0 + wr * 32 + mt * 16 + lr;
        const int r1 = r0 + 8;
#pragma unroll
        for (int nt = 0; nt < 8; nt++) {
            const int col = wc * 64 + nt * 8 + lc * 2;
            float d0 = acc[mt][nt][0], d1 = acc[mt][nt][1];
            float d2 = acc[mt][nt][2], d3 = acc[mt][nt][3];
            if (bias != nullptr) {
                const float2 bv = *(const float2*)(bias + col);
                d0 += bv.x; d1 += bv.y; d2 += bv.x; d3 += bv.y;
            }
            if (EPI == 1) {
                if (r0 < rows) {
                    const float keep = (rowscale[r0] > 0.f) ? (1.f - kAlpha) : 0.f;
                    const float2 xv = *(const float2*)(x0 + (size_t)r0 * kD + col);
                    *(float2*)(C + (size_t)r0 * kD + col) =
                        make_float2(keep * d0 + kAlpha * xv.x, keep * d1 + kAlpha * xv.y);
                }
                if (r1 < rows) {
                    const float keep = (rowscale[r1] > 0.f) ? (1.f - kAlpha) : 0.f;
                    const float2 xv = *(const float2*)(x0 + (size_t)r1 * kD + col);
                    *(float2*)(C + (size_t)r1 * kD + col) =
                        make_float2(keep * d2 + kAlpha * xv.x, keep * d3 + kAlpha * xv.y);
                }
            } else {
                if (r0 < rows)
                    *(float2*)(C + (size_t)r0 * kD + col) = make_float2(d0, d1);
                if (r1 < rows)
                    *(float2*)(C + (size_t)r1 * kD + col) = make_float2(d2, d3);
            }
        }
    }
}

// ---------------------------------------------------------------------------
// Row-wise LayerNorm + ReLU in place: warp per row.
// ---------------------------------------------------------------------------
__global__ __launch_bounds__(256)
void lnrelu_kernel(float* __restrict__ H, const float* __restrict__ g,
                   const float* __restrict__ be, int rows)
{
    const int w    = (blockIdx.x * blockDim.x + threadIdx.x) >> 5;
    const int lane = threadIdx.x & 31;
    if (w >= rows) return;
    float4* p = (float4*)(H + (size_t)w * kD + lane * 4);
    float4 v = *p;
    float s  = v.x + v.y + v.z + v.w;
    float s2 = v.x * v.x + v.y * v.y + v.z * v.z + v.w * v.w;
#pragma unroll
    for (int o = 16; o >= 1; o >>= 1) {
        s  += __shfl_xor_sync(0xffffffffu, s,  o);
        s2 += __shfl_xor_sync(0xffffffffu, s2, o);
    }
    const float mu   = s * (1.f / 128.f);
    const float var  = s2 * (1.f / 128.f) - mu * mu;
    const float rstd = rsqrtf(var + kEps);
    const float4 gg = *(const float4*)(g + lane * 4);
    const float4 bt = *(const float4*)(be + lane * 4);
    v.x = fmaxf((v.x - mu) * rstd * gg.x + bt.x, 0.f);
    v.y = fmaxf((v.y - mu) * rstd * gg.y + bt.y, 0.f);
    v.z = fmaxf((v.z - mu) * rstd * gg.z + bt.z, 0.f);
    v.w = fmaxf((v.w - mu) * rstd * gg.w + bt.w, 0.f);
    *p = v;
}

// ---------------------------------------------------------------------------
// Pass 1: warp per incidence -> atomic accumulate Y1[v] into Xe[e] + count
// ---------------------------------------------------------------------------
__global__ __launch_bounds__(256)
void scatter_edge_kernel()
{
    const int gw   = (blockIdx.x * blockDim.x + threadIdx.x) >> 5;
    const int lane = threadIdx.x & 31;
    if (gw >= kM) return;
    const int v = g_vi[gw];
    const int e = g_ej[gw];
    const float4 val = *(const float4*)(g_Y1 + (size_t)v * kD + lane * 4);
    red_add_f32x4(g_Xe + (size_t)e * kD + lane * 4, val);
    if (lane == 0) atomicAdd(&g_ecnt[e], 1.0f);
}

// ---------------------------------------------------------------------------
// Pass 2: h = relu(LN(P[v]+Q[e]+b2_1)); atomic accumulate into S[v] + count
// ---------------------------------------------------------------------------
__global__ __launch_bounds__(256)
void inc2_kernel(const float* __restrict__ b1,
                 const float* __restrict__ g,
                 const float* __restrict__ be)
{
    const int gw   = (blockIdx.x * blockDim.x + threadIdx.x) >> 5;
    const int lane = threadIdx.x & 31;
    if (gw >= kM) return;
    const int v = g_vi[gw];
    const int e = g_ej[gw];
    const int c = lane * 4;

    const float4 p  = *(const float4*)(g_P + (size_t)v * kD + c);
    const float4 q  = *(const float4*)(g_Q + (size_t)e * kD + c);
    const float4 bb = *(const float4*)(b1 + c);

    const float h0 = p.x + q.x + bb.x;
    const float h1 = p.y + q.y + bb.y;
    const float h2 = p.z + q.z + bb.z;
    const float h3 = p.w + q.w + bb.w;

    float s  = h0 + h1 + h2 + h3;
    float s2 = h0 * h0 + h1 * h1 + h2 * h2 + h3 * h3;
#pragma unroll
    for (int o = 16; o >= 1; o >>= 1) {
        s  += __shfl_xor_sync(0xffffffffu, s,  o);
        s2 += __shfl_xor_sync(0xffffffffu, s2, o);
    }
    const float mu   = s * (1.f / 128.f);
    const float var  = s2 * (1.f / 128.f) - mu * mu;
    const float rstd = rsqrtf(var + kEps);

    const float4 gg = *(const float4*)(g + c);
    const float4 bt = *(const float4*)(be + c);

    float4 o;
    o.x = fmaxf((h0 - mu) * rstd * gg.x + bt.x, 0.f);
    o.y = fmaxf((h1 - mu) * rstd * gg.y + bt.y, 0.f);
    o.z = fmaxf((h2 - mu) * rstd * gg.z + bt.z, 0.f);
    o.w = fmaxf((h3 - mu) * rstd * gg.w + bt.w, 0.f);

    red_add_f32x4(g_S + (size_t)v * kD + c, o);
    if (lane == 0) atomicAdd(&g_vcnt[v], 1.0f);
}

// ---------------------------------------------------------------------------
extern "C" void kernel_launch(void* const* d_in, const int* in_sizes, int n_in,
                              void* d_out, int out_size)
{
    const float* x    = (const float*)d_in[0];
    const float* w1_1 = (const float*)d_in[1];
    const float* b1_1 = (const float*)d_in[2];
    const float* g1   = (const float*)d_in[3];
    const float* be1  = (const float*)d_in[4];
    const float* w1_2 = (const float*)d_in[5];
    const float* b1_2 = (const float*)d_in[6];
    const float* w2_1 = (const float*)d_in[7];
    const float* b2_1 = (const float*)d_in[8];
    const float* g2   = (const float*)d_in[9];
    const float* be2  = (const float*)d_in[10];
    const float* w2_2 = (const float*)d_in[11];
    const float* b2_2 = (const float*)d_in[12];
    const void*  ei   = d_in[13];
    float* out = (float*)d_out;

    float *H1, *Y1, *P, *S, *Xe, *Q, *ecnt, *vcnt;
    cudaGetSymbolAddress((void**)&H1,   g_H1);
    cudaGetSymbolAddress((void**)&Y1,   g_Y1);
    cudaGetSymbolAddress((void**)&P,    g_P);
    cudaGetSymbolAddress((void**)&S,    g_S);
    cudaGetSymbolAddress((void**)&Xe,   g_Xe);
    cudaGetSymbolAddress((void**)&Q,    g_Q);
    cudaGetSymbolAddress((void**)&ecnt, g_ecnt);
    cudaGetSymbolAddress((void**)&vcnt, g_vcnt);

    const int gbN = (kN + 127) / 128;   // 313
    const int gbE = (kE + 127) / 128;   // 157
    const int incBlocks = kM / 8;       // 80000

    probe_kernel<<<1, 32>>>((const int*)ei);
    decode_kernel<<<(kM + 255) / 256, 256>>>(ei);
    zero_kernel<<<2048, 256>>>();

    // H1 = x @ w1_1 + b1_1 ; then in-place LN+ReLU -> T1
    gemm_tf32<0><<<gbN, 256>>>(x, w1_1, b1_1, nullptr, nullptr, H1, kN);
    lnrelu_kernel<<<(kN * 32 + 255) / 256, 256>>>(H1, g1, be1, kN);
    // Y1 = T1 @ w1_2 + b1_2
    gemm_tf32<0><<<gbN, 256>>>(H1, w1_2, b1_2, nullptr, nullptr, Y1, kN);
    // P = x @ W2a (bias folded into inc2)
    gemm_tf32<0><<<gbN, 256>>>(x, w2_1, nullptr, nullptr, nullptr, P, kN);
    // Xe_sum += Y1[vertex]; edge counts
    scatter_edge_kernel<<<incBlocks, 256>>>();
    // Q = (Xe_sum / max(ecnt,1)) @ W2b   (divide folded into A-load)
    gemm_tf32<0><<<gbE, 256>>>(Xe, w2_1 + 128 * 128, nullptr, ecnt, nullptr, Q, kE);
    // S += relu(LN(P[v] + Q[e] + b2_1)); vertex counts
    inc2_kernel<<<incBlocks, 256>>>(b2_1, g2, be2);
    // out = (1-a)*mask(vcnt>0)*((S/max(vcnt,1)) @ w2_2 + b2_2) + a*x
    gemm_tf32<1><<<gbN, 256>>>(S, w2_2, b2_2, vcnt, x, out, kN);
}

// round 4
// speedup vs baseline: 1.7056x; 1.1300x over previous
#include <cuda_runtime.h>
#include <cstdint>

// ---------------------------------------------------------------------------
// EquivDiffusion: hypergraph two-stage MLP diffusion, CSR-based (atomic-free
// scatter-means), tf32 tensor-core GEMMs.
//   Y1 = MLP1(x)                         (N rows)
//   Xe[e] = mean_{v in e} Y1[v]          (warp-per-edge gather reduce)
//   P = x @ W2a ; Q = Xe @ W2b           (split of w2_1 over concat)
//   S[v] = mean_{e in v} relu(LN(P[v]+Q[e]+b2_1))   (warp-per-vertex)
//   out = (1-a)*mask(deg(v)>0)*(S @ w2_2 + b2_2) + a*x
// ---------------------------------------------------------------------------

namespace {
constexpr int   kN = 40000;
constexpr int   kE = 20000;
constexpr int   kM = 640000;
constexpr int   kD = 128;
constexpr float kAlpha = 0.1f;
constexpr float kEps   = 1e-5f;
}

__device__ __align__(16) float g_H1[kN * kD];
__device__ __align__(16) float g_Y1[kN * kD];
__device__ __align__(16) float g_P [kN * kD];
__device__ __align__(16) float g_S [kN * kD];
__device__ __align__(16) float g_Xe[kE * kD];
__device__ __align__(16) float g_Q [kE * kD];
__device__ float g_vcntf[kN];
__device__ int   g_vi[kM], g_ej[kM];
__device__ int   g_ecnt[kE], g_vcnt[kN];
__device__ int   g_eoff[kE + 1], g_voff[kN + 1];
__device__ int   g_ecur[kE], g_vcur[kN];
__device__ int   g_eadj[kM];     // vertices grouped by edge
__device__ int   g_vadj[kM];     // edges grouped by vertex
__device__ int   g_is64;

// ---------------------------------------------------------------------------
__device__ __forceinline__ uint32_t f2tf32(float f)
{
    uint32_t u;
    asm("cvt.rna.tf32.f32 %0, %1;" : "=r"(u) : "f"(f));
    return u;
}

__device__ __forceinline__ void mma_tf32(float* d, const uint32_t* a, const uint32_t* b)
{
    asm volatile(
        "mma.sync.aligned.m16n8k8.row.col.f32.tf32.tf32.f32 "
        "{%0,%1,%2,%3}, {%4,%5,%6,%7}, {%8,%9}, {%0,%1,%2,%3};"
        : "+f"(d[0]), "+f"(d[1]), "+f"(d[2]), "+f"(d[3])
        : "r"(a[0]), "r"(a[1]), "r"(a[2]), "r"(a[3]), "r"(b[0]), "r"(b[1]));
}

// ---------------------------------------------------------------------------
// Probe int64 vs int32 edge_index. Samples only within the first kM 4-byte
// words (in-bounds for BOTH layouts).
// ---------------------------------------------------------------------------
__global__ void probe_kernel(const int* __restrict__ ei_as_i32)
{
    if (threadIdx.x != 0 || blockIdx.x != 0) return;
    int all_zero_high = 1;
    for (int k = 0; k < 128; k++) {
        const int idx = k * (kM / 512);            // idx < kM/4
        if (ei_as_i32[2 * idx + 1] != 0) { all_zero_high = 0; break; }
    }
    g_is64 = all_zero_high;
}

// ---------------------------------------------------------------------------
__global__ __launch_bounds__(256)
void zero_hist_kernel()
{
    const int stride = gridDim.x * blockDim.x;
    const int t = blockIdx.x * blockDim.x + threadIdx.x;
    for (int i = t; i < kE; i += stride) { g_ecnt[i] = 0; g_ecur[i] = 0; }
    for (int i = t; i < kN; i += stride) { g_vcnt[i] = 0; g_vcur[i] = 0; }
}

// Decode indices + histogram.
__global__ __launch_bounds__(256)
void decode_kernel(const void* __restrict__ ei)
{
    const int t = blockIdx.x * blockDim.x + threadIdx.x;
    if (t >= kM) return;
    int v, e;
    if (g_is64) {
        const long long* p = (const long long*)ei;
        v = (int)p[t];
        e = (int)p[kM + t];
    } else {
        const int* p = (const int*)ei;
        v = p[t];
        e = p[kM + t];
    }
    g_vi[t] = v;
    g_ej[t] = e;
    atomicAdd(&g_ecnt[e], 1);
    atomicAdd(&g_vcnt[v], 1);
}

// Exclusive scan: block 0 -> edges, block 1 -> vertices. 1024 threads.
__global__ __launch_bounds__(1024)
void scan_kernel()
{
    __shared__ int partial[1024];
    const int tid = threadIdx.x;
    const int n    = (blockIdx.x == 0) ? kE : kN;
    const int* cnt = (blockIdx.x == 0) ? g_ecnt : g_vcnt;
    int*       off = (blockIdx.x == 0) ? g_eoff : g_voff;
    const int chunk = (n + 1023) / 1024;
    const int beg = tid * chunk;
    const int end = min(beg + chunk, n);
    int s = 0;
    for (int i = beg; i < end; i++) s += cnt[i];
    partial[tid] = s;
    __syncthreads();
    for (int o = 1; o < 1024; o <<= 1) {
        const int v = (tid >= o) ? partial[tid - o] : 0;
        __syncthreads();
        partial[tid] += v;
        __syncthreads();
    }
    int base = partial[tid] - s;
    for (int i = beg; i < end; i++) { off[i] = base; base += cnt[i]; }
    if (tid == 0) off[n] = partial[1023];
}

// Scatter incidences into adjacency lists.
__global__ __launch_bounds__(256)
void build_kernel()
{
    const int t = blockIdx.x * blockDim.x + threadIdx.x;
    if (t >= kM) return;
    const int v = g_vi[t];
    const int e = g_ej[t];
    const int pe = g_eoff[e] + atomicAdd(&g_ecur[e], 1);
    g_eadj[pe] = v;
    const int pv = g_voff[v] + atomicAdd(&g_vcur[v], 1);
    g_vadj[pv] = e;
}

// ---------------------------------------------------------------------------
// tf32 GEMM body: C[rows,128] = A[rows,128] @ B[128,128] (+bias).
// tf32 conversion done at SMEM staging. 8 warps (4x2), warp tile 32x64.
// EPI==1: out = keep(row)*acc + alpha*x0, keep = (keepcnt>0 ? 1-alpha : 0)
// ---------------------------------------------------------------------------
template <int EPI>
__device__ __forceinline__
void gemm_body(const float* __restrict__ A, const float* __restrict__ B,
               const float* __restrict__ bias, const float* __restrict__ x0,
               const float* __restrict__ keepcnt, float* __restrict__ C,
               int rows, int tile)
{
    __shared__ uint32_t As[2][128][20];
    __shared__ uint32_t Bs[2][16][136];

    const int t    = threadIdx.x;
    const int lane = t & 31;
    const int wid  = t >> 5;
    const int wr   = wid & 3;
    const int wc   = wid >> 2;
    const int lr   = lane >> 2;
    const int lc   = lane & 3;
    const int row0 = tile * 128;

    const int arow = row0 + (t >> 1);
    const bool aval = (arow < rows);
    const float* Ap = A + (size_t)arow * kD + (t & 1) * 8;
    const float* Bp = B + (size_t)(t >> 4) * kD + (t & 15) * 8;

    float acc[2][8][4];
#pragma unroll
    for (int mt = 0; mt < 2; mt++)
#pragma unroll
        for (int nt = 0; nt < 8; nt++)
#pragma unroll
            for (int i = 0; i < 4; i++) acc[mt][nt][i] = 0.f;

    float4 pa0, pa1, pb0, pb1;
    if (aval) { pa0 = *(const float4*)Ap; pa1 = *(const float4*)(Ap + 4); }
    else { pa0 = make_float4(0,0,0,0); pa1 = make_float4(0,0,0,0); }
    pb0 = *(const float4*)Bp; pb1 = *(const float4*)(Bp + 4);
    {
        uint32_t* as = &As[0][t >> 1][(t & 1) * 8];
        as[0] = f2tf32(pa0.x); as[1] = f2tf32(pa0.y); as[2] = f2tf32(pa0.z); as[3] = f2tf32(pa0.w);
        as[4] = f2tf32(pa1.x); as[5] = f2tf32(pa1.y); as[6] = f2tf32(pa1.z); as[7] = f2tf32(pa1.w);
        uint32_t* bs = &Bs[0][t >> 4][(t & 15) * 8];
        bs[0] = f2tf32(pb0.x); bs[1] = f2tf32(pb0.y); bs[2] = f2tf32(pb0.z); bs[3] = f2tf32(pb0.w);
        bs[4] = f2tf32(pb1.x); bs[5] = f2tf32(pb1.y); bs[6] = f2tf32(pb1.z); bs[7] = f2tf32(pb1.w);
    }
    __syncthreads();

    for (int s = 0; s < 8; s++) {
        const int buf = s & 1;
        if (s < 7) {
            if (aval) {
                const float* ap = Ap + (s + 1) * 16;
                pa0 = *(const float4*)ap; pa1 = *(const float4*)(ap + 4);
            }
            const float* bp = Bp + (size_t)(s + 1) * 16 * kD;
            pb0 = *(const float4*)bp; pb1 = *(const float4*)(bp + 4);
        }
#pragma unroll
        for (int h = 0; h < 2; h++) {
            const int ks = h * 8;
            uint32_t af[2][4];
#pragma unroll
            for (int mt = 0; mt < 2; mt++) {
                const int rb = wr * 32 + mt * 16;
                af[mt][0] = As[buf][rb + lr][ks + lc];
                af[mt][1] = As[buf][rb + lr + 8][ks + lc];
                af[mt][2] = As[buf][rb + lr][ks + lc + 4];
                af[mt][3] = As[buf][rb + lr + 8][ks + lc + 4];
            }
            uint32_t bfr[8][2];
#pragma unroll
            for (int nt = 0; nt < 8; nt++) {
                const int cb = wc * 64 + nt * 8;
                bfr[nt][0] = Bs[buf][ks + lc][cb + lr];
                bfr[nt][1] = Bs[buf][ks + lc + 4][cb + lr];
            }
#pragma unroll
            for (int mt = 0; mt < 2; mt++)
#pragma unroll
                for (int nt = 0; nt < 8; nt++)
                    mma_tf32(acc[mt][nt], af[mt], bfr[nt]);
        }
        if (s < 7) {
            const int nb = buf ^ 1;
            uint32_t* as = &As[nb][t >> 1][(t & 1) * 8];
            as[0] = f2tf32(pa0.x); as[1] = f2tf32(pa0.y); as[2] = f2tf32(pa0.z); as[3] = f2tf32(pa0.w);
            as[4] = f2tf32(pa1.x); as[5] = f2tf32(pa1.y); as[6] = f2tf32(pa1.z); as[7] = f2tf32(pa1.w);
            uint32_t* bs = &Bs[nb][t >> 4][(t & 15) * 8];
            bs[0] = f2tf32(pb0.x); bs[1] = f2tf32(pb0.y); bs[2] = f2tf32(pb0.z); bs[3] = f2tf32(pb0.w);
            bs[4] = f2tf32(pb1.x); bs[5] = f2tf32(pb1.y); bs[6] = f2tf32(pb1.z); bs[7] = f2tf32(pb1.w);
            __syncthreads();
        }
    }

#pragma unroll
    for (int mt = 0; mt < 2; mt++) {
        const int r0 = row0 + wr * 32 + mt * 16 + lr;
        const int r1 = r0 + 8;
#pragma unroll
        for (int nt = 0; nt < 8; nt++) {
            const int col = wc * 64 + nt * 8 + lc * 2;
            float d0 = acc[mt][nt][0], d1 = acc[mt][nt][1];
            float d2 = acc[mt][nt][2], d3 = acc[mt][nt][3];
            if (bias != nullptr) {
                const float2 bv = *(const float2*)(bias + col);
                d0 += bv.x; d1 += bv.y; d2 += bv.x; d3 += bv.y;
            }
            if (EPI == 1) {
                if (r0 < rows) {
                    const float keep = (keepcnt[r0] > 0.f) ? (1.f - kAlpha) : 0.f;
                    const float2 xv = *(const float2*)(x0 + (size_t)r0 * kD + col);
                    *(float2*)(C + (size_t)r0 * kD + col) =
                        make_float2(keep * d0 + kAlpha * xv.x, keep * d1 + kAlpha * xv.y);
                }
                if (r1 < rows) {
                    const float keep = (keepcnt[r1] > 0.f) ? (1.f - kAlpha) : 0.f;
                    const float2 xv = *(const float2*)(x0 + (size_t)r1 * kD + col);
                    *(float2*)(C + (size_t)r1 * kD + col) =
                        make_float2(keep * d2 + kAlpha * xv.x, keep * d3 + kAlpha * xv.y);
                }
            } else {
                if (r0 < rows) *(float2*)(C + (size_t)r0 * kD + col) = make_float2(d0, d1);
                if (r1 < rows) *(float2*)(C + (size_t)r1 * kD + col) = make_float2(d2, d3);
            }
        }
    }
}

template <int EPI>
__global__ __launch_bounds__(256)
void gemm_tf32(const float* __restrict__ A, const float* __restrict__ B,
               const float* __restrict__ bias, const float* __restrict__ x0,
               const float* __restrict__ keepcnt, float* __restrict__ C, int rows)
{
    gemm_body<EPI>(A, B, bias, x0, keepcnt, C, rows, blockIdx.x);
}

// Two GEMMs sharing A, selected by blockIdx.y (amortizes the wave tail).
__global__ __launch_bounds__(256)
void gemm_dual(const float* __restrict__ A,
               const float* __restrict__ B0, const float* __restrict__ bias0,
               float* __restrict__ C0,
               const float* __restrict__ B1, float* __restrict__ C1, int rows)
{
    if (blockIdx.y == 0)
        gemm_body<0>(A, B0, bias0, nullptr, nullptr, C0, rows, blockIdx.x);
    else
        gemm_body<0>(A, B1, nullptr, nullptr, nullptr, C1, rows, blockIdx.x);
}

// ---------------------------------------------------------------------------
// Row-wise LayerNorm + ReLU in place: warp per row.
// ---------------------------------------------------------------------------
__global__ __launch_bounds__(256)
void lnrelu_kernel(float* __restrict__ H, const float* __restrict__ g,
                   const float* __restrict__ be, int rows)
{
    const int w    = (blockIdx.x * blockDim.x + threadIdx.x) >> 5;
    const int lane = threadIdx.x & 31;
    if (w >= rows) return;
    float4* p = (float4*)(H + (size_t)w * kD) + lane;
    float4 v = *p;
    float s  = v.x + v.y + v.z + v.w;
    float s2 = v.x * v.x + v.y * v.y + v.z * v.z + v.w * v.w;
#pragma unroll
    for (int o = 16; o >= 1; o >>= 1) {
        s  += __shfl_xor_sync(0xffffffffu, s,  o);
        s2 += __shfl_xor_sync(0xffffffffu, s2, o);
    }
    const float mu   = s * (1.f / 128.f);
    const float var  = s2 * (1.f / 128.f) - mu * mu;
    const float rstd = rsqrtf(var + kEps);
    const float4 gg = *((const float4*)g + lane);
    const float4 bt = *((const float4*)be + lane);
    v.x = fmaxf((v.x - mu) * rstd * gg.x + bt.x, 0.f);
    v.y = fmaxf((v.y - mu) * rstd * gg.y + bt.y, 0.f);
    v.z = fmaxf((v.z - mu) * rstd * gg.z + bt.z, 0.f);
    v.w = fmaxf((v.w - mu) * rstd * gg.w + bt.w, 0.f);
    *p = v;
}

// ---------------------------------------------------------------------------
// Pass 1: warp per edge: Xe[e] = mean over member vertices of Y1.
// ---------------------------------------------------------------------------
__global__ __launch_bounds__(256)
void edge_reduce_kernel()
{
    const int e    = (blockIdx.x * blockDim.x + threadIdx.x) >> 5;
    const int lane = threadIdx.x & 31;
    if (e >= kE) return;
    const int beg = g_eoff[e], end = g_eoff[e + 1];
    float4 acc = make_float4(0.f, 0.f, 0.f, 0.f);
    int j = beg;
    for (; j + 1 < end; j += 2) {
        const int v0 = g_eadj[j];
        const int v1 = g_eadj[j + 1];
        const float4 a = *((const float4*)(g_Y1 + (size_t)v0 * kD) + lane);
        const float4 b = *((const float4*)(g_Y1 + (size_t)v1 * kD) + lane);
        acc.x += a.x + b.x; acc.y += a.y + b.y;
        acc.z += a.z + b.z; acc.w += a.w + b.w;
    }
    if (j < end) {
        const int v0 = g_eadj[j];
        const float4 a = *((const float4*)(g_Y1 + (size_t)v0 * kD) + lane);
        acc.x += a.x; acc.y += a.y; acc.z += a.z; acc.w += a.w;
    }
    const float inv = 1.f / fmaxf((float)(end - beg), 1.f);
    acc.x *= inv; acc.y *= inv; acc.z *= inv; acc.w *= inv;
    *((float4*)(g_Xe + (size_t)e * kD) + lane) = acc;
}

// ---------------------------------------------------------------------------
// Pass 2: warp per vertex: S[v] = mean over incident edges of
//         relu(LN(P[v] + Q[e] + b2_1)); also record degree.
// ---------------------------------------------------------------------------
__global__ __launch_bounds__(256)
void vertex_pass_kernel(const float* __restrict__ b1,
                        const float* __restrict__ g,
                        const float* __restrict__ be)
{
    const int v    = (blockIdx.x * blockDim.x + threadIdx.x) >> 5;
    const int lane = threadIdx.x & 31;
    if (v >= kN) return;
    const int beg = g_voff[v], end = g_voff[v + 1];
    const int cnt = end - beg;

    float4 pr = *((const float4*)(g_P + (size_t)v * kD) + lane);
    const float4 bb = *((const float4*)b1 + lane);
    pr.x += bb.x; pr.y += bb.y; pr.z += bb.z; pr.w += bb.w;
    const float4 gg = *((const float4*)g + lane);
    const float4 bt = *((const float4*)be + lane);

    float4 acc = make_float4(0.f, 0.f, 0.f, 0.f);
    for (int j = beg; j < end; j++) {
        const int e = g_vadj[j];
        const float4 q = *((const float4*)(g_Q + (size_t)e * kD) + lane);
        const float h0 = pr.x + q.x;
        const float h1 = pr.y + q.y;
        const float h2 = pr.z + q.z;
        const float h3 = pr.w + q.w;
        float s  = h0 + h1 + h2 + h3;
        float s2 = h0 * h0 + h1 * h1 + h2 * h2 + h3 * h3;
#pragma unroll
        for (int o = 16; o >= 1; o >>= 1) {
            s  += __shfl_xor_sync(0xffffffffu, s,  o);
            s2 += __shfl_xor_sync(0xffffffffu, s2, o);
        }
        const float mu   = s * (1.f / 128.f);
        const float var  = s2 * (1.f / 128.f) - mu * mu;
        const float rstd = rsqrtf(var + kEps);
        acc.x += fmaxf((h0 - mu) * rstd * gg.x + bt.x, 0.f);
        acc.y += fmaxf((h1 - mu) * rstd * gg.y + bt.y, 0.f);
        acc.z += fmaxf((h2 - mu) * rstd * gg.z + bt.z, 0.f);
        acc.w += fmaxf((h3 - mu) * rstd * gg.w + bt.w, 0.f);
    }
    const float inv = 1.f / fmaxf((float)cnt, 1.f);
    acc.x *= inv; acc.y *= inv; acc.z *= inv; acc.w *= inv;
    *((float4*)(g_S + (size_t)v * kD) + lane) = acc;
    if (lane == 0) g_vcntf[v] = (float)cnt;
}

// ---------------------------------------------------------------------------
extern "C" void kernel_launch(void* const* d_in, const int* in_sizes, int n_in,
                              void* d_out, int out_size)
{
    const float* x    = (const float*)d_in[0];
    const float* w1_1 = (const float*)d_in[1];
    const float* b1_1 = (const float*)d_in[2];
    const float* g1   = (const float*)d_in[3];
    const float* be1  = (const float*)d_in[4];
    const float* w1_2 = (const float*)d_in[5];
    const float* b1_2 = (const float*)d_in[6];
    const float* w2_1 = (const float*)d_in[7];
    const float* b2_1 = (const float*)d_in[8];
    const float* g2   = (const float*)d_in[9];
    const float* be2  = (const float*)d_in[10];
    const float* w2_2 = (const float*)d_in[11];
    const float* b2_2 = (const float*)d_in[12];
    const void*  ei   = d_in[13];
    float* out = (float*)d_out;

    float *H1, *Y1, *P, *S, *Xe, *Q, *vcntf;
    cudaGetSymbolAddress((void**)&H1,    g_H1);
    cudaGetSymbolAddress((void**)&Y1,    g_Y1);
    cudaGetSymbolAddress((void**)&P,     g_P);
    cudaGetSymbolAddress((void**)&S,     g_S);
    cudaGetSymbolAddress((void**)&Xe,    g_Xe);
    cudaGetSymbolAddress((void**)&Q,     g_Q);
    cudaGetSymbolAddress((void**)&vcntf, g_vcntf);

    const int gbN = (kN + 127) / 128;   // 313
    const int gbE = (kE + 127) / 128;   // 157

    // ---- index decode + CSR build ----
    probe_kernel<<<1, 32>>>((const int*)ei);
    zero_hist_kernel<<<256, 256>>>();
    decode_kernel<<<(kM + 255) / 256, 256>>>(ei);
    scan_kernel<<<2, 1024>>>();
    build_kernel<<<(kM + 255) / 256, 256>>>();

    // ---- H1 = x@w1_1 + b1_1  and  P = x@W2a (fused launch, shared A) ----
    gemm_dual<<<dim3(gbN, 2), 256>>>(x, w1_1, b1_1, H1, w2_1, P, kN);
    // T1 = relu(LN(H1)) in place
    lnrelu_kernel<<<(kN * 32 + 255) / 256, 256>>>(H1, g1, be1, kN);
    // Y1 = T1 @ w1_2 + b1_2
    gemm_tf32<0><<<gbN, 256>>>(H1, w1_2, b1_2, nullptr, nullptr, Y1, kN);
    // Xe[e] = mean of Y1 over members
    edge_reduce_kernel<<<(kE * 32 + 255) / 256, 256>>>();
    // Q = Xe @ W2b
    gemm_tf32<0><<<gbE, 256>>>(Xe, w2_1 + 128 * 128, nullptr, nullptr, nullptr, Q, kE);
    // S[v] = mean over edges of relu(LN(P[v]+Q[e]+b2_1)); degree -> vcntf
    vertex_pass_kernel<<<(kN * 32 + 255) / 256, 256>>>(b2_1, g2, be2);
    // out = (1-a)*mask*(S@w2_2 + b2_2) + a*x
    gemm_tf32<1><<<gbN, 256>>>(S, w2_2, b2_2, x, vcntf, out, kN);
}

// round 5
// speedup vs baseline: 2.0247x; 1.1871x over previous
#include <cuda_runtime.h>
#include <cstdint>

// ---------------------------------------------------------------------------
// EquivDiffusion: hypergraph two-stage MLP diffusion, CSR-based (atomic-free
// scatter-means), tf32 tensor-core GEMMs, LN fused into GEMM epilogue.
//   H1 = relu(LN(x @ w1_1 + b1_1))       (fused epilogue)
//   Y1 = H1 @ w1_2 + b1_2
//   Xe[e] = mean_{v in e} Y1[v]          (warp-per-edge gather reduce)
//   P = x @ W2a ; Q = Xe @ W2b           (split of w2_1 over concat)
//   S[v] = mean_{e in v} relu(LN(P[v]+Q[e]+b2_1))   (warp-per-vertex)
//   out = (1-a)*mask(deg(v)>0)*(S @ w2_2 + b2_2) + a*x
// ---------------------------------------------------------------------------

namespace {
constexpr int   kN = 40000;
constexpr int   kE = 20000;
constexpr int   kM = 640000;
constexpr int   kD = 128;
constexpr float kAlpha = 0.1f;
constexpr float kEps   = 1e-5f;
constexpr int   kNB_E = (kE + 1023) / 1024;   // 20
constexpr int   kNB_V = (kN + 1023) / 1024;   // 40
}

__device__ __align__(16) float g_H1[kN * kD];
__device__ __align__(16) float g_Y1[kN * kD];
__device__ __align__(16) float g_P [kN * kD];
__device__ __align__(16) float g_S [kN * kD];
__device__ __align__(16) float g_Xe[kE * kD];
__device__ __align__(16) float g_Q [kE * kD];
__device__ float g_vcntf[kN];
__device__ int   g_vi[kM], g_ej[kM];
__device__ __align__(16) int g_ecnt[kE];
__device__ __align__(16) int g_vcnt[kN];
__device__ __align__(16) int g_eoff[kE + 4];
__device__ __align__(16) int g_voff[kN + 4];
__device__ int   g_ecur[kE], g_vcur[kN];
__device__ int   g_eadj[kM];     // vertices grouped by edge
__device__ int   g_vadj[kM];     // edges grouped by vertex
__device__ int   g_bsume[64], g_bsumv[64];
__device__ int   g_is64;

// ---------------------------------------------------------------------------
__device__ __forceinline__ uint32_t f2tf32(float f)
{
    uint32_t u;
    asm("cvt.rna.tf32.f32 %0, %1;" : "=r"(u) : "f"(f));
    return u;
}

__device__ __forceinline__ void mma_tf32(float* d, const uint32_t* a, const uint32_t* b)
{
    asm volatile(
        "mma.sync.aligned.m16n8k8.row.col.f32.tf32.tf32.f32 "
        "{%0,%1,%2,%3}, {%4,%5,%6,%7}, {%8,%9}, {%0,%1,%2,%3};"
        : "+f"(d[0]), "+f"(d[1]), "+f"(d[2]), "+f"(d[3])
        : "r"(a[0]), "r"(a[1]), "r"(a[2]), "r"(a[3]), "r"(b[0]), "r"(b[1]));
}

// ---------------------------------------------------------------------------
// Probe int64 vs int32 edge_index (samples in-bounds for both layouts).
// ---------------------------------------------------------------------------
__global__ void probe_kernel(const int* __restrict__ ei_as_i32)
{
    if (threadIdx.x != 0 || blockIdx.x != 0) return;
    int all_zero_high = 1;
    for (int k = 0; k < 128; k++) {
        const int idx = k * (kM / 512);
        if (ei_as_i32[2 * idx + 1] != 0) { all_zero_high = 0; break; }
    }
    g_is64 = all_zero_high;
}

__global__ __launch_bounds__(256)
void zero_hist_kernel()
{
    const int stride = gridDim.x * blockDim.x;
    const int t = blockIdx.x * blockDim.x + threadIdx.x;
    for (int i = t; i < kE; i += stride) { g_ecnt[i] = 0; g_ecur[i] = 0; }
    for (int i = t; i < kN; i += stride) { g_vcnt[i] = 0; g_vcur[i] = 0; }
}

__global__ __launch_bounds__(256)
void decode_kernel(const void* __restrict__ ei)
{
    const int t = blockIdx.x * blockDim.x + threadIdx.x;
    if (t >= kM) return;
    int v, e;
    if (g_is64) {
        const long long* p = (const long long*)ei;
        v = (int)p[t];
        e = (int)p[kM + t];
    } else {
        const int* p = (const int*)ei;
        v = p[t];
        e = p[kM + t];
    }
    g_vi[t] = v;
    g_ej[t] = e;
    atomicAdd(&g_ecnt[e], 1);
    atomicAdd(&g_vcnt[v], 1);
}

// ---------------------------------------------------------------------------
// 3-phase exclusive scan over g_ecnt (y=0) and g_vcnt (y=1).
// Phase 1: per-block (1024 elems, 256 thr x 4) exclusive scan + block sum.
// ---------------------------------------------------------------------------
__global__ __launch_bounds__(256)
void scan1_kernel()
{
    __shared__ int sh[256];
    const int which = blockIdx.y;
    const int n     = which ? kN : kE;
    const int* cnt  = which ? g_vcnt : g_ecnt;
    int* off        = which ? g_voff : g_eoff;
    int* bsum       = which ? g_bsumv : g_bsume;
    const int base  = blockIdx.x * 1024;
    if (base >= n) return;
    const int tid = threadIdx.x;
    const int idx = base + tid * 4;

    int4 a = make_int4(0, 0, 0, 0);
    if (idx < n) a = *(const int4*)(cnt + idx);     // n % 4 == 0 for both
    const int t0 = a.x;
    const int t1 = t0 + a.y;
    const int t2 = t1 + a.z;
    const int t3 = t2 + a.w;
    sh[tid] = t3;
    __syncthreads();
#pragma unroll
    for (int o = 1; o < 256; o <<= 1) {
        const int u = (tid >= o) ? sh[tid - o] : 0;
        __syncthreads();
        sh[tid] += u;
        __syncthreads();
    }
    const int prev = sh[tid] - t3;
    if (idx < n) *(int4*)(off + idx) = make_int4(prev, prev + t0, prev + t1, prev + t2);
    if (tid == 255) bsum[blockIdx.x] = sh[255];
}

// Phase 2: scan of block sums (<=64 each) + totals into off[n].
__global__ __launch_bounds__(64)
void scan2_kernel()
{
    __shared__ int sh[64];
    const int tid = threadIdx.x;
    // edges
    int v = (tid < kNB_E) ? g_bsume[tid] : 0;
    sh[tid] = v;
    __syncthreads();
#pragma unroll
    for (int o = 1; o < 64; o <<= 1) {
        const int u = (tid >= o) ? sh[tid - o] : 0;
        __syncthreads();
        sh[tid] += u;
        __syncthreads();
    }
    if (tid < kNB_E) g_bsume[tid] = sh[tid] - v;
    if (tid == 63) g_eoff[kE] = sh[63];
    __syncthreads();
    // vertices
    v = (tid < kNB_V) ? g_bsumv[tid] : 0;
    sh[tid] = v;
    __syncthreads();
#pragma unroll
    for (int o = 1; o < 64; o <<= 1) {
        const int u = (tid >= o) ? sh[tid - o] : 0;
        __syncthreads();
        sh[tid] += u;
        __syncthreads();
    }
    if (tid < kNB_V) g_bsumv[tid] = sh[tid] - v;
    if (tid == 63) g_voff[kN] = sh[63];
}

// Phase 3: add scanned block offsets back.
__global__ __launch_bounds__(256)
void scan3_kernel()
{
    const int which = blockIdx.y;
    const int n     = which ? kN : kE;
    int* off        = which ? g_voff : g_eoff;
    const int* bsum = which ? g_bsumv : g_bsume;
    const int base  = blockIdx.x * 1024;
    if (base >= n || blockIdx.x == 0) return;
    const int add = bsum[blockIdx.x];
    const int idx = base + threadIdx.x * 4;
    if (idx < n) {
        int4 o = *(int4*)(off + idx);
        o.x += add; o.y += add; o.z += add; o.w += add;
        *(int4*)(off + idx) = o;
    }
}

// Scatter incidences into adjacency lists.
__global__ __launch_bounds__(256)
void build_kernel()
{
    const int t = blockIdx.x * blockDim.x + threadIdx.x;
    if (t >= kM) return;
    const int v = g_vi[t];
    const int e = g_ej[t];
    const int pe = g_eoff[e] + atomicAdd(&g_ecur[e], 1);
    g_eadj[pe] = v;
    const int pv = g_voff[v] + atomicAdd(&g_vcur[v], 1);
    g_vadj[pv] = e;
}

// ---------------------------------------------------------------------------
// tf32 GEMM body: C[rows,128] = A[rows,128] @ B[128,128] (+bias).
// 8 warps (4x2), warp tile 32x64, tf32 conversion at SMEM staging.
// EPI==0: plain.  EPI==1: out = keep(row)*acc + alpha*x0 (aux0=x0, aux1=cnt).
// EPI==2: out = relu(LN(acc)) with gamma=aux0, beta=aux1 (fused LayerNorm;
//         the 128-wide tile covers full rows -> 4-lane shfl + smem exchange).
// ---------------------------------------------------------------------------
template <int EPI>
__device__ __forceinline__
void gemm_body(const float* __restrict__ A, const float* __restrict__ B,
               const float* __restrict__ bias, const float* __restrict__ aux0,
               const float* __restrict__ aux1, float* __restrict__ C,
               int rows, int tile)
{
    __shared__ uint32_t As[2][128][20];
    __shared__ uint32_t Bs[2][16][136];
    __shared__ float2   red[128][2];    // [row][wc] = (sum, sumsq) for EPI==2

    const int t    = threadIdx.x;
    const int lane = t & 31;
    const int wid  = t >> 5;
    const int wr   = wid & 3;
    const int wc   = wid >> 2;
    const int lr   = lane >> 2;
    const int lc   = lane & 3;
    const int row0 = tile * 128;

    const int arow = row0 + (t >> 1);
    const bool aval = (arow < rows);
    const float* Ap = A + (size_t)arow * kD + (t & 1) * 8;
    const float* Bp = B + (size_t)(t >> 4) * kD + (t & 15) * 8;

    float acc[2][8][4];
#pragma unroll
    for (int mt = 0; mt < 2; mt++)
#pragma unroll
        for (int nt = 0; nt < 8; nt++)
#pragma unroll
            for (int i = 0; i < 4; i++) acc[mt][nt][i] = 0.f;

    float4 pa0 = make_float4(0,0,0,0), pa1 = make_float4(0,0,0,0), pb0, pb1;
    if (aval) { pa0 = *(const float4*)Ap; pa1 = *(const float4*)(Ap + 4); }
    pb0 = *(const float4*)Bp; pb1 = *(const float4*)(Bp + 4);
    {
        uint32_t* as = &As[0][t >> 1][(t & 1) * 8];
        as[0] = f2tf32(pa0.x); as[1] = f2tf32(pa0.y); as[2] = f2tf32(pa0.z); as[3] = f2tf32(pa0.w);
        as[4] = f2tf32(pa1.x); as[5] = f2tf32(pa1.y); as[6] = f2tf32(pa1.z); as[7] = f2tf32(pa1.w);
        uint32_t* bs = &Bs[0][t >> 4][(t & 15) * 8];
        bs[0] = f2tf32(pb0.x); bs[1] = f2tf32(pb0.y); bs[2] = f2tf32(pb0.z); bs[3] = f2tf32(pb0.w);
        bs[4] = f2tf32(pb1.x); bs[5] = f2tf32(pb1.y); bs[6] = f2tf32(pb1.z); bs[7] = f2tf32(pb1.w);
    }
    __syncthreads();

    for (int s = 0; s < 8; s++) {
        const int buf = s & 1;
        if (s < 7) {
            if (aval) {
                const float* ap = Ap + (s + 1) * 16;
                pa0 = *(const float4*)ap; pa1 = *(const float4*)(ap + 4);
            }
            const float* bp = Bp + (size_t)(s + 1) * 16 * kD;
            pb0 = *(const float4*)bp; pb1 = *(const float4*)(bp + 4);
        }
#pragma unroll
        for (int h = 0; h < 2; h++) {
            const int ks = h * 8;
            uint32_t af[2][4];
#pragma unroll
            for (int mt = 0; mt < 2; mt++) {
                const int rb = wr * 32 + mt * 16;
                af[mt][0] = As[buf][rb + lr][ks + lc];
                af[mt][1] = As[buf][rb + lr + 8][ks + lc];
                af[mt][2] = As[buf][rb + lr][ks + lc + 4];
                af[mt][3] = As[buf][rb + lr + 8][ks + lc + 4];
            }
            uint32_t bfr[8][2];
#pragma unroll
            for (int nt = 0; nt < 8; nt++) {
                const int cb = wc * 64 + nt * 8;
                bfr[nt][0] = Bs[buf][ks + lc][cb + lr];
                bfr[nt][1] = Bs[buf][ks + lc + 4][cb + lr];
            }
#pragma unroll
            for (int mt = 0; mt < 2; mt++)
#pragma unroll
                for (int nt = 0; nt < 8; nt++)
                    mma_tf32(acc[mt][nt], af[mt], bfr[nt]);
        }
        if (s < 7) {
            const int nb = buf ^ 1;
            uint32_t* as = &As[nb][t >> 1][(t & 1) * 8];
            as[0] = f2tf32(pa0.x); as[1] = f2tf32(pa0.y); as[2] = f2tf32(pa0.z); as[3] = f2tf32(pa0.w);
            as[4] = f2tf32(pa1.x); as[5] = f2tf32(pa1.y); as[6] = f2tf32(pa1.z); as[7] = f2tf32(pa1.w);
            uint32_t* bs = &Bs[nb][t >> 4][(t & 15) * 8];
            bs[0] = f2tf32(pb0.x); bs[1] = f2tf32(pb0.y); bs[2] = f2tf32(pb0.z); bs[3] = f2tf32(pb0.w);
            bs[4] = f2tf32(pb1.x); bs[5] = f2tf32(pb1.y); bs[6] = f2tf32(pb1.z); bs[7] = f2tf32(pb1.w);
            __syncthreads();
        }
    }

    // ---- bias add (in place) ----
    if (bias != nullptr) {
#pragma unroll
        for (int nt = 0; nt < 8; nt++) {
            const float2 bv = *(const float2*)(bias + wc * 64 + nt * 8 + lc * 2);
#pragma unroll
            for (int mt = 0; mt < 2; mt++) {
                acc[mt][nt][0] += bv.x; acc[mt][nt][1] += bv.y;
                acc[mt][nt][2] += bv.x; acc[mt][nt][3] += bv.y;
            }
        }
    }

    if (EPI == 2) {
        // fused LayerNorm + ReLU across the full 128-col row
        float s_[2][2], q_[2][2];
#pragma unroll
        for (int mt = 0; mt < 2; mt++) {
            s_[mt][0] = s_[mt][1] = q_[mt][0] = q_[mt][1] = 0.f;
#pragma unroll
            for (int nt = 0; nt < 8; nt++) {
                s_[mt][0] += acc[mt][nt][0] + acc[mt][nt][1];
                q_[mt][0] += acc[mt][nt][0] * acc[mt][nt][0] + acc[mt][nt][1] * acc[mt][nt][1];
                s_[mt][1] += acc[mt][nt][2] + acc[mt][nt][3];
                q_[mt][1] += acc[mt][nt][2] * acc[mt][nt][2] + acc[mt][nt][3] * acc[mt][nt][3];
            }
        }
#pragma unroll
        for (int o = 1; o <= 2; o <<= 1) {
#pragma unroll
            for (int mt = 0; mt < 2; mt++)
#pragma unroll
                for (int r = 0; r < 2; r++) {
                    s_[mt][r] += __shfl_xor_sync(0xffffffffu, s_[mt][r], o);
                    q_[mt][r] += __shfl_xor_sync(0xffffffffu, q_[mt][r], o);
                }
        }
        if (lc == 0) {
#pragma unroll
            for (int mt = 0; mt < 2; mt++) {
                red[wr * 32 + mt * 16 + lr][wc]     = make_float2(s_[mt][0], q_[mt][0]);
                red[wr * 32 + mt * 16 + lr + 8][wc] = make_float2(s_[mt][1], q_[mt][1]);
            }
        }
        __syncthreads();
#pragma unroll
        for (int mt = 0; mt < 2; mt++) {
            const int rl0 = wr * 32 + mt * 16 + lr;
            const float2 a0 = red[rl0][0],     b0 = red[rl0][1];
            const float2 a1 = red[rl0 + 8][0], b1 = red[rl0 + 8][1];
            const float mu0 = (a0.x + b0.x) * (1.f / 128.f);
            const float mu1 = (a1.x + b1.x) * (1.f / 128.f);
            const float rs0 = rsqrtf((a0.y + b0.y) * (1.f / 128.f) - mu0 * mu0 + kEps);
            const float rs1 = rsqrtf((a1.y + b1.y) * (1.f / 128.f) - mu1 * mu1 + kEps);
            const int r0 = row0 + rl0, r1 = r0 + 8;
#pragma unroll
            for (int nt = 0; nt < 8; nt++) {
                const int col = wc * 64 + nt * 8 + lc * 2;
                const float2 gm = *(const float2*)(aux0 + col);
                const float2 bt = *(const float2*)(aux1 + col);
                if (r0 < rows) {
                    const float v0 = fmaxf((acc[mt][nt][0] - mu0) * rs0 * gm.x + bt.x, 0.f);
                    const float v1 = fmaxf((acc[mt][nt][1] - mu0) * rs0 * gm.y + bt.y, 0.f);
                    *(float2*)(C + (size_t)r0 * kD + col) = make_float2(v0, v1);
                }
                if (r1 < rows) {
                    const float v2 = fmaxf((acc[mt][nt][2] - mu1) * rs1 * gm.x + bt.x, 0.f);
                    const float v3 = fmaxf((acc[mt][nt][3] - mu1) * rs1 * gm.y + bt.y, 0.f);
                    *(float2*)(C + (size_t)r1 * kD + col) = make_float2(v2, v3);
                }
            }
        }
        return;
    }

#pragma unroll
    for (int mt = 0; mt < 2; mt++) {
        const int r0 = row0 + wr * 32 + mt * 16 + lr;
        const int r1 = r0 + 8;
#pragma unroll
        for (int nt = 0; nt < 8; nt++) {
            const int col = wc * 64 + nt * 8 + lc * 2;
            const float d0 = acc[mt][nt][0], d1 = acc[mt][nt][1];
            const float d2 = acc[mt][nt][2], d3 = acc[mt][nt][3];
            if (EPI == 1) {
                if (r0 < rows) {
                    const float keep = (aux1[r0] > 0.f) ? (1.f - kAlpha) : 0.f;
                    const float2 xv = *(const float2*)(aux0 + (size_t)r0 * kD + col);
                    *(float2*)(C + (size_t)r0 * kD + col) =
                        make_float2(keep * d0 + kAlpha * xv.x, keep * d1 + kAlpha * xv.y);
                }
                if (r1 < rows) {
                    const float keep = (aux1[r1] > 0.f) ? (1.f - kAlpha) : 0.f;
                    const float2 xv = *(const float2*)(aux0 + (size_t)r1 * kD + col);
                    *(float2*)(C + (size_t)r1 * kD + col) =
                        make_float2(keep * d2 + kAlpha * xv.x, keep * d3 + kAlpha * xv.y);
                }
            } else {
                if (r0 < rows) *(float2*)(C + (size_t)r0 * kD + col) = make_float2(d0, d1);
                if (r1 < rows) *(float2*)(C + (size_t)r1 * kD + col) = make_float2(d2, d3);
            }
        }
    }
}

template <int EPI>
__global__ __launch_bounds__(256)
void gemm_tf32(const float* __restrict__ A, const float* __restrict__ B,
               const float* __restrict__ bias, const float* __restrict__ aux0,
               const float* __restrict__ aux1, float* __restrict__ C, int rows)
{
    gemm_body<EPI>(A, B, bias, aux0, aux1, C, rows, blockIdx.x);
}

// Two GEMMs sharing A: y==0 -> H1 with fused LN+ReLU, y==1 -> P plain.
__global__ __launch_bounds__(256)
void gemm_dual(const float* __restrict__ A,
               const float* __restrict__ B0, const float* __restrict__ bias0,
               const float* __restrict__ g0, const float* __restrict__ be0,
               float* __restrict__ C0,
               const float* __restrict__ B1, float* __restrict__ C1, int rows)
{
    if (blockIdx.y == 0)
        gemm_body<2>(A, B0, bias0, g0, be0, C0, rows, blockIdx.x);
    else
        gemm_body<0>(A, B1, nullptr, nullptr, nullptr, C1, rows, blockIdx.x);
}

// ---------------------------------------------------------------------------
// Pass 1: warp per edge: Xe[e] = mean over member vertices of Y1.
// ---------------------------------------------------------------------------
__global__ __launch_bounds__(256)
void edge_reduce_kernel()
{
    const int e    = (blockIdx.x * blockDim.x + threadIdx.x) >> 5;
    const int lane = threadIdx.x & 31;
    if (e >= kE) return;
    const int beg = g_eoff[e], end = g_eoff[e + 1];
    float4 acc = make_float4(0.f, 0.f, 0.f, 0.f);
    int j = beg;
    for (; j + 1 < end; j += 2) {
        const int v0 = g_eadj[j];
        const int v1 = g_eadj[j + 1];
        const float4 a = *((const float4*)(g_Y1 + (size_t)v0 * kD) + lane);
        const float4 b = *((const float4*)(g_Y1 + (size_t)v1 * kD) + lane);
        acc.x += a.x + b.x; acc.y += a.y + b.y;
        acc.z += a.z + b.z; acc.w += a.w + b.w;
    }
    if (j < end) {
        const int v0 = g_eadj[j];
        const float4 a = *((const float4*)(g_Y1 + (size_t)v0 * kD) + lane);
        acc.x += a.x; acc.y += a.y; acc.z += a.z; acc.w += a.w;
    }
    const float inv = 1.f / fmaxf((float)(end - beg), 1.f);
    acc.x *= inv; acc.y *= inv; acc.z *= inv; acc.w *= inv;
    *((float4*)(g_Xe + (size_t)e * kD) + lane) = acc;
}

// ---------------------------------------------------------------------------
// Pass 2: warp per vertex: S[v] = mean over incident edges of
//         relu(LN(P[v] + Q[e] + b2_1)); also record degree.
// ---------------------------------------------------------------------------
__global__ __launch_bounds__(256)
void vertex_pass_kernel(const float* __restrict__ b1,
                        const float* __restrict__ g,
                        const float* __restrict__ be)
{
    const int v    = (blockIdx.x * blockDim.x + threadIdx.x) >> 5;
    const int lane = threadIdx.x & 31;
    if (v >= kN) return;
    const int beg = g_voff[v], end = g_voff[v + 1];
    const int cnt = end - beg;

    float4 pr = *((const float4*)(g_P + (size_t)v * kD) + lane);
    const float4 bb = *((const float4*)b1 + lane);
    pr.x += bb.x; pr.y += bb.y; pr.z += bb.z; pr.w += bb.w;
    const float4 gg = *((const float4*)g + lane);
    const float4 bt = *((const float4*)be + lane);

    float4 acc = make_float4(0.f, 0.f, 0.f, 0.f);
    for (int j = beg; j < end; j++) {
        const int e = g_vadj[j];
        const float4 q = *((const float4*)(g_Q + (size_t)e * kD) + lane);
        const float h0 = pr.x + q.x;
        const float h1 = pr.y + q.y;
        const float h2 = pr.z + q.z;
        const float h3 = pr.w + q.w;
        float s  = h0 + h1 + h2 + h3;
        float s2 = h0 * h0 + h1 * h1 + h2 * h2 + h3 * h3;
#pragma unroll
        for (int o = 16; o >= 1; o >>= 1) {
            s  += __shfl_xor_sync(0xffffffffu, s,  o);
            s2 += __shfl_xor_sync(0xffffffffu, s2, o);
        }
        const float mu   = s * (1.f / 128.f);
        const float var  = s2 * (1.f / 128.f) - mu * mu;
        const float rstd = rsqrtf(var + kEps);
        acc.x += fmaxf((h0 - mu) * rstd * gg.x + bt.x, 0.f);
        acc.y += fmaxf((h1 - mu) * rstd * gg.y + bt.y, 0.f);
        acc.z += fmaxf((h2 - mu) * rstd * gg.z + bt.z, 0.f);
        acc.w += fmaxf((h3 - mu) * rstd * gg.w + bt.w, 0.f);
    }
    const float inv = 1.f / fmaxf((float)cnt, 1.f);
    acc.x *= inv; acc.y *= inv; acc.z *= inv; acc.w *= inv;
    *((float4*)(g_S + (size_t)v * kD) + lane) = acc;
    if (lane == 0) g_vcntf[v] = (float)cnt;
}

// ---------------------------------------------------------------------------
extern "C" void kernel_launch(void* const* d_in, const int* in_sizes, int n_in,
                              void* d_out, int out_size)
{
    const float* x    = (const float*)d_in[0];
    const float* w1_1 = (const float*)d_in[1];
    const float* b1_1 = (const float*)d_in[2];
    const float* g1   = (const float*)d_in[3];
    const float* be1  = (const float*)d_in[4];
    const float* w1_2 = (const float*)d_in[5];
    const float* b1_2 = (const float*)d_in[6];
    const float* w2_1 = (const float*)d_in[7];
    const float* b2_1 = (const float*)d_in[8];
    const float* g2   = (const float*)d_in[9];
    const float* be2  = (const float*)d_in[10];
    const float* w2_2 = (const float*)d_in[11];
    const float* b2_2 = (const float*)d_in[12];
    const void*  ei   = d_in[13];
    float* out = (float*)d_out;

    float *H1, *Y1, *P, *S, *Xe, *Q, *vcntf;
    cudaGetSymbolAddress((void**)&H1,    g_H1);
    cudaGetSymbolAddress((void**)&Y1,    g_Y1);
    cudaGetSymbolAddress((void**)&P,     g_P);
    cudaGetSymbolAddress((void**)&S,     g_S);
    cudaGetSymbolAddress((void**)&Xe,    g_Xe);
    cudaGetSymbolAddress((void**)&Q,     g_Q);
    cudaGetSymbolAddress((void**)&vcntf, g_vcntf);

    const int gbN = (kN + 127) / 128;   // 313
    const int gbE = (kE + 127) / 128;   // 157

    // ---- index decode + CSR build ----
    probe_kernel<<<1, 32>>>((const int*)ei);
    zero_hist_kernel<<<256, 256>>>();
    decode_kernel<<<(kM + 255) / 256, 256>>>(ei);
    scan1_kernel<<<dim3(kNB_V, 2), 256>>>();
    scan2_kernel<<<1, 64>>>();
    scan3_kernel<<<dim3(kNB_V, 2), 256>>>();
    build_kernel<<<(kM + 255) / 256, 256>>>();

    // ---- H1 = relu(LN(x@w1_1+b1_1)) (fused) and P = x@W2a, shared A ----
    gemm_dual<<<dim3(gbN, 2), 256>>>(x, w1_1, b1_1, g1, be1, H1, w2_1, P, kN);
    // Y1 = H1 @ w1_2 + b1_2
    gemm_tf32<0><<<gbN, 256>>>(H1, w1_2, b1_2, nullptr, nullptr, Y1, kN);
    // Xe[e] = mean of Y1 over members
    edge_reduce_kernel<<<(kE * 32 + 255) / 256, 256>>>();
    // Q = Xe @ W2b
    gemm_tf32<0><<<gbE, 256>>>(Xe, w2_1 + 128 * 128, nullptr, nullptr, nullptr, Q, kE);
    // S[v] = mean over edges of relu(LN(P[v]+Q[e]+b2_1)); degree -> vcntf
    vertex_pass_kernel<<<(kN * 32 + 255) / 256, 256>>>(b2_1, g2, be2);
    // out = (1-a)*mask*(S@w2_2 + b2_2) + a*x
    gemm_tf32<1><<<gbN, 256>>>(S, w2_2, b2_2, x, vcntf, out, kN);
}

// round 6
// speedup vs baseline: 2.2006x; 1.0869x over previous
#include <cuda_runtime.h>
#include <cstdint>

// ---------------------------------------------------------------------------
// EquivDiffusion: hypergraph two-stage MLP diffusion.
//   H1 = relu(LN(x @ w1_1 + b1_1))            (fused LN epilogue)
//   Xepre[e] = mean_{v in e} H1[v]            (warp-per-edge gather)
//   Q = Xepre @ (w1_2 @ W2b) + (b1_2 @ W2b)   (GEMM composition: Y1/Xe gone)
//   P = x @ W2a + b2_1                        (bias folded)
//   S[v] = mean_{e in v} relu(LN(P[v]+Q[e]))  (warp-per-vertex, stats trick)
//   out = (1-a)*mask(deg>0)*(S @ w2_2 + b2_2) + a*x
// ---------------------------------------------------------------------------

namespace {
constexpr int   kN = 40000;
constexpr int   kE = 20000;
constexpr int   kM = 640000;
constexpr int   kD = 128;
constexpr float kAlpha = 0.1f;
constexpr float kEps   = 1e-5f;
constexpr int   kNB_E = (kE + 1023) / 1024;   // 20
constexpr int   kNB_V = (kN + 1023) / 1024;   // 40
}

__device__ __align__(16) float g_H1[kN * kD];
__device__ __align__(16) float g_P [kN * kD];
__device__ __align__(16) float g_S [kN * kD];
__device__ __align__(16) float g_Xe[kE * kD];   // Xepre
__device__ __align__(16) float g_Q [kE * kD];
__device__ __align__(16) float g_Wc[kD * kD];   // w1_2 @ W2b
__device__ __align__(16) float g_bc[kD];        // b1_2 @ W2b
__device__ __align__(16) float2 g_pstat[kN];    // (sum, sumsq) of P rows
__device__ __align__(16) float2 g_qstat[kE];    // (sum, sumsq) of Q rows
__device__ float g_vcntf[kN];
__device__ int   g_vi[kM], g_ej[kM];
__device__ __align__(16) int g_ecnt[kE];
__device__ __align__(16) int g_vcnt[kN];
__device__ __align__(16) int g_eoff[kE + 4];
__device__ __align__(16) int g_voff[kN + 4];
__device__ int   g_ecur[kE], g_vcur[kN];
__device__ int   g_eadj[kM];     // vertices grouped by edge
__device__ int   g_vadj[kM];     // edges grouped by vertex
__device__ int   g_bsume[64], g_bsumv[64];
__device__ int   g_is64;

// ---------------------------------------------------------------------------
__device__ __forceinline__ uint32_t f2tf32(float f)
{
    uint32_t u;
    asm("cvt.rna.tf32.f32 %0, %1;" : "=r"(u) : "f"(f));
    return u;
}

__device__ __forceinline__ void mma_tf32(float* d, const uint32_t* a, const uint32_t* b)
{
    asm volatile(
        "mma.sync.aligned.m16n8k8.row.col.f32.tf32.tf32.f32 "
        "{%0,%1,%2,%3}, {%4,%5,%6,%7}, {%8,%9}, {%0,%1,%2,%3};"
        : "+f"(d[0]), "+f"(d[1]), "+f"(d[2]), "+f"(d[3])
        : "r"(a[0]), "r"(a[1]), "r"(a[2]), "r"(a[3]), "r"(b[0]), "r"(b[1]));
}

// ---------------------------------------------------------------------------
// zero hists + (block 0) probe int64 vs int32 edge_index.
// ---------------------------------------------------------------------------
__global__ __launch_bounds__(256)
void zero_hist_kernel(const int* __restrict__ ei_as_i32)
{
    const int stride = gridDim.x * blockDim.x;
    const int t = blockIdx.x * blockDim.x + threadIdx.x;
    for (int i = t; i < kE; i += stride) { g_ecnt[i] = 0; g_ecur[i] = 0; }
    for (int i = t; i < kN; i += stride) { g_vcnt[i] = 0; g_vcur[i] = 0; }
    if (blockIdx.x == 0 && threadIdx.x == 0) {
        int all_zero_high = 1;
        for (int k = 0; k < 128; k++) {
            const int idx = k * (kM / 512);          // in-bounds for both layouts
            if (ei_as_i32[2 * idx + 1] != 0) { all_zero_high = 0; break; }
        }
        g_is64 = all_zero_high;
    }
}

__global__ __launch_bounds__(256)
void decode_kernel(const void* __restrict__ ei)
{
    const int t = blockIdx.x * blockDim.x + threadIdx.x;
    if (t >= kM) return;
    int v, e;
    if (g_is64) {
        const long long* p = (const long long*)ei;
        v = (int)p[t];
        e = (int)p[kM + t];
    } else {
        const int* p = (const int*)ei;
        v = p[t];
        e = p[kM + t];
    }
    g_vi[t] = v;
    g_ej[t] = e;
    atomicAdd(&g_ecnt[e], 1);
    atomicAdd(&g_vcnt[v], 1);
}

// ---------------------------------------------------------------------------
// 3-phase exclusive scan over g_ecnt (y=0) and g_vcnt (y=1).
// ---------------------------------------------------------------------------
__global__ __launch_bounds__(256)
void scan1_kernel()
{
    __shared__ int sh[256];
    const int which = blockIdx.y;
    const int n     = which ? kN : kE;
    const int* cnt  = which ? g_vcnt : g_ecnt;
    int* off        = which ? g_voff : g_eoff;
    int* bsum       = which ? g_bsumv : g_bsume;
    const int base  = blockIdx.x * 1024;
    if (base >= n) return;
    const int tid = threadIdx.x;
    const int idx = base + tid * 4;

    int4 a = make_int4(0, 0, 0, 0);
    if (idx < n) a = *(const int4*)(cnt + idx);
    const int t0 = a.x;
    const int t1 = t0 + a.y;
    const int t2 = t1 + a.z;
    const int t3 = t2 + a.w;
    sh[tid] = t3;
    __syncthreads();
#pragma unroll
    for (int o = 1; o < 256; o <<= 1) {
        const int u = (tid >= o) ? sh[tid - o] : 0;
        __syncthreads();
        sh[tid] += u;
        __syncthreads();
    }
    const int prev = sh[tid] - t3;
    if (idx < n) *(int4*)(off + idx) = make_int4(prev, prev + t0, prev + t1, prev + t2);
    if (tid == 255) bsum[blockIdx.x] = sh[255];
}

__global__ __launch_bounds__(64)
void scan2_kernel()
{
    __shared__ int sh[64];
    const int tid = threadIdx.x;
    int v = (tid < kNB_E) ? g_bsume[tid] : 0;
    sh[tid] = v;
    __syncthreads();
#pragma unroll
    for (int o = 1; o < 64; o <<= 1) {
        const int u = (tid >= o) ? sh[tid - o] : 0;
        __syncthreads();
        sh[tid] += u;
        __syncthreads();
    }
    if (tid < kNB_E) g_bsume[tid] = sh[tid] - v;
    if (tid == 63) g_eoff[kE] = sh[63];
    __syncthreads();
    v = (tid < kNB_V) ? g_bsumv[tid] : 0;
    sh[tid] = v;
    __syncthreads();
#pragma unroll
    for (int o = 1; o < 64; o <<= 1) {
        const int u = (tid >= o) ? sh[tid - o] : 0;
        __syncthreads();
        sh[tid] += u;
        __syncthreads();
    }
    if (tid < kNB_V) g_bsumv[tid] = sh[tid] - v;
    if (tid == 63) g_voff[kN] = sh[63];
}

__global__ __launch_bounds__(256)
void scan3_kernel()
{
    const int which = blockIdx.y;
    const int n     = which ? kN : kE;
    int* off        = which ? g_voff : g_eoff;
    const int* bsum = which ? g_bsumv : g_bsume;
    const int base  = blockIdx.x * 1024;
    if (base >= n || blockIdx.x == 0) return;
    const int add = bsum[blockIdx.x];
    const int idx = base + threadIdx.x * 4;
    if (idx < n) {
        int4 o = *(int4*)(off + idx);
        o.x += add; o.y += add; o.z += add; o.w += add;
        *(int4*)(off + idx) = o;
    }
}

__global__ __launch_bounds__(256)
void build_kernel()
{
    const int t = blockIdx.x * blockDim.x + threadIdx.x;
    if (t >= kM) return;
    const int v = g_vi[t];
    const int e = g_ej[t];
    const int pe = g_eoff[e] + atomicAdd(&g_ecur[e], 1);
    g_eadj[pe] = v;
    const int pv = g_voff[v] + atomicAdd(&g_vcur[v], 1);
    g_vadj[pv] = e;
}

// ---------------------------------------------------------------------------
// tf32 GEMM body: C[rows,128] = A[rows,128] @ B[128,128] (+bias).
// EPI==0: plain.
// EPI==1: out = keep(row)*acc + alpha*aux0 row (aux1 = count array).
// EPI==2: out = relu(LN(acc)), gamma=aux0, beta=aux1 (full-row LN).
// EPI==3: plain store + per-row (sum, sumsq) written to stat.
// ---------------------------------------------------------------------------
template <int EPI>
__device__ __forceinline__
void gemm_body(const float* __restrict__ A, const float* __restrict__ B,
               const float* __restrict__ bias, const float* __restrict__ aux0,
               const float* __restrict__ aux1, float2* __restrict__ stat,
               float* __restrict__ C, int rows, int tile)
{
    __shared__ uint32_t As[2][128][20];
    __shared__ uint32_t Bs[2][16][136];
    __shared__ float2   red[128][2];

    const int t    = threadIdx.x;
    const int lane = t & 31;
    const int wid  = t >> 5;
    const int wr   = wid & 3;
    const int wc   = wid >> 2;
    const int lr   = lane >> 2;
    const int lc   = lane & 3;
    const int row0 = tile * 128;

    const int arow = row0 + (t >> 1);
    const bool aval = (arow < rows);
    const float* Ap = A + (size_t)arow * kD + (t & 1) * 8;
    const float* Bp = B + (size_t)(t >> 4) * kD + (t & 15) * 8;

    float acc[2][8][4];
#pragma unroll
    for (int mt = 0; mt < 2; mt++)
#pragma unroll
        for (int nt = 0; nt < 8; nt++)
#pragma unroll
            for (int i = 0; i < 4; i++) acc[mt][nt][i] = 0.f;

    float4 pa0 = make_float4(0,0,0,0), pa1 = make_float4(0,0,0,0), pb0, pb1;
    if (aval) { pa0 = *(const float4*)Ap; pa1 = *(const float4*)(Ap + 4); }
    pb0 = *(const float4*)Bp; pb1 = *(const float4*)(Bp + 4);
    {
        uint32_t* as = &As[0][t >> 1][(t & 1) * 8];
        as[0] = f2tf32(pa0.x); as[1] = f2tf32(pa0.y); as[2] = f2tf32(pa0.z); as[3] = f2tf32(pa0.w);
        as[4] = f2tf32(pa1.x); as[5] = f2tf32(pa1.y); as[6] = f2tf32(pa1.z); as[7] = f2tf32(pa1.w);
        uint32_t* bs = &Bs[0][t >> 4][(t & 15) * 8];
        bs[0] = f2tf32(pb0.x); bs[1] = f2tf32(pb0.y); bs[2] = f2tf32(pb0.z); bs[3] = f2tf32(pb0.w);
        bs[4] = f2tf32(pb1.x); bs[5] = f2tf32(pb1.y); bs[6] = f2tf32(pb1.z); bs[7] = f2tf32(pb1.w);
    }
    __syncthreads();

    for (int s = 0; s < 8; s++) {
        const int buf = s & 1;
        if (s < 7) {
            if (aval) {
                const float* ap = Ap + (s + 1) * 16;
                pa0 = *(const float4*)ap; pa1 = *(const float4*)(ap + 4);
            }
            const float* bp = Bp + (size_t)(s + 1) * 16 * kD;
            pb0 = *(const float4*)bp; pb1 = *(const float4*)(bp + 4);
        }
#pragma unroll
        for (int h = 0; h < 2; h++) {
            const int ks = h * 8;
            uint32_t af[2][4];
#pragma unroll
            for (int mt = 0; mt < 2; mt++) {
                const int rb = wr * 32 + mt * 16;
                af[mt][0] = As[buf][rb + lr][ks + lc];
                af[mt][1] = As[buf][rb + lr + 8][ks + lc];
                af[mt][2] = As[buf][rb + lr][ks + lc + 4];
                af[mt][3] = As[buf][rb + lr + 8][ks + lc + 4];
            }
            uint32_t bfr[8][2];
#pragma unroll
            for (int nt = 0; nt < 8; nt++) {
                const int cb = wc * 64 + nt * 8;
                bfr[nt][0] = Bs[buf][ks + lc][cb + lr];
                bfr[nt][1] = Bs[buf][ks + lc + 4][cb + lr];
            }
#pragma unroll
            for (int mt = 0; mt < 2; mt++)
#pragma unroll
                for (int nt = 0; nt < 8; nt++)
                    mma_tf32(acc[mt][nt], af[mt], bfr[nt]);
        }
        if (s < 7) {
            const int nb = buf ^ 1;
            uint32_t* as = &As[nb][t >> 1][(t & 1) * 8];
            as[0] = f2tf32(pa0.x); as[1] = f2tf32(pa0.y); as[2] = f2tf32(pa0.z); as[3] = f2tf32(pa0.w);
            as[4] = f2tf32(pa1.x); as[5] = f2tf32(pa1.y); as[6] = f2tf32(pa1.z); as[7] = f2tf32(pa1.w);
            uint32_t* bs = &Bs[nb][t >> 4][(t & 15) * 8];
            bs[0] = f2tf32(pb0.x); bs[1] = f2tf32(pb0.y); bs[2] = f2tf32(pb0.z); bs[3] = f2tf32(pb0.w);
            bs[4] = f2tf32(pb1.x); bs[5] = f2tf32(pb1.y); bs[6] = f2tf32(pb1.z); bs[7] = f2tf32(pb1.w);
            __syncthreads();
        }
    }

    if (bias != nullptr) {
#pragma unroll
        for (int nt = 0; nt < 8; nt++) {
            const float2 bv = *(const float2*)(bias + wc * 64 + nt * 8 + lc * 2);
#pragma unroll
            for (int mt = 0; mt < 2; mt++) {
                acc[mt][nt][0] += bv.x; acc[mt][nt][1] += bv.y;
                acc[mt][nt][2] += bv.x; acc[mt][nt][3] += bv.y;
            }
        }
    }

    if (EPI == 2 || EPI == 3) {
        // per-row (sum, sumsq) across the full 128-col row
        float s_[2][2], q_[2][2];
#pragma unroll
        for (int mt = 0; mt < 2; mt++) {
            s_[mt][0] = s_[mt][1] = q_[mt][0] = q_[mt][1] = 0.f;
#pragma unroll
            for (int nt = 0; nt < 8; nt++) {
                s_[mt][0] += acc[mt][nt][0] + acc[mt][nt][1];
                q_[mt][0] += acc[mt][nt][0] * acc[mt][nt][0] + acc[mt][nt][1] * acc[mt][nt][1];
                s_[mt][1] += acc[mt][nt][2] + acc[mt][nt][3];
                q_[mt][1] += acc[mt][nt][2] * acc[mt][nt][2] + acc[mt][nt][3] * acc[mt][nt][3];
            }
        }
#pragma unroll
        for (int o = 1; o <= 2; o <<= 1) {
#pragma unroll
            for (int mt = 0; mt < 2; mt++)
#pragma unroll
                for (int r = 0; r < 2; r++) {
                    s_[mt][r] += __shfl_xor_sync(0xffffffffu, s_[mt][r], o);
                    q_[mt][r] += __shfl_xor_sync(0xffffffffu, q_[mt][r], o);
                }
        }
        if (lc == 0) {
#pragma unroll
            for (int mt = 0; mt < 2; mt++) {
                red[wr * 32 + mt * 16 + lr][wc]     = make_float2(s_[mt][0], q_[mt][0]);
                red[wr * 32 + mt * 16 + lr + 8][wc] = make_float2(s_[mt][1], q_[mt][1]);
            }
        }
        __syncthreads();
    }

    if (EPI == 2) {
#pragma unroll
        for (int mt = 0; mt < 2; mt++) {
            const int rl0 = wr * 32 + mt * 16 + lr;
            const float2 a0 = red[rl0][0],     b0 = red[rl0][1];
            const float2 a1 = red[rl0 + 8][0], b1 = red[rl0 + 8][1];
            const float mu0 = (a0.x + b0.x) * (1.f / 128.f);
            const float mu1 = (a1.x + b1.x) * (1.f / 128.f);
            const float rs0 = rsqrtf((a0.y + b0.y) * (1.f / 128.f) - mu0 * mu0 + kEps);
            const float rs1 = rsqrtf((a1.y + b1.y) * (1.f / 128.f) - mu1 * mu1 + kEps);
            const int r0 = row0 + rl0, r1 = r0 + 8;
#pragma unroll
            for (int nt = 0; nt < 8; nt++) {
                const int col = wc * 64 + nt * 8 + lc * 2;
                const float2 gm = *(const float2*)(aux0 + col);
                const float2 bt = *(const float2*)(aux1 + col);
                if (r0 < rows) {
                    const float v0 = fmaxf((acc[mt][nt][0] - mu0) * rs0 * gm.x + bt.x, 0.f);
                    const float v1 = fmaxf((acc[mt][nt][1] - mu0) * rs0 * gm.y + bt.y, 0.f);
                    *(float2*)(C + (size_t)r0 * kD + col) = make_float2(v0, v1);
                }
                if (r1 < rows) {
                    const float v2 = fmaxf((acc[mt][nt][2] - mu1) * rs1 * gm.x + bt.x, 0.f);
                    const float v3 = fmaxf((acc[mt][nt][3] - mu1) * rs1 * gm.y + bt.y, 0.f);
                    *(float2*)(C + (size_t)r1 * kD + col) = make_float2(v2, v3);
                }
            }
        }
        return;
    }

    if (EPI == 3) {
        if (wc == 0 && lc == 0) {
#pragma unroll
            for (int mt = 0; mt < 2; mt++) {
                const int rl0 = mt == 0 ? (wr * 32 + lr) : (wr * 32 + 16 + lr);
                const int r0 = row0 + rl0;
                if (r0 < rows)
                    stat[r0] = make_float2(red[rl0][0].x + red[rl0][1].x,
                                           red[rl0][0].y + red[rl0][1].y);
                const int r1 = r0 + 8;
                if (r1 < rows)
                    stat[r1] = make_float2(red[rl0 + 8][0].x + red[rl0 + 8][1].x,
                                           red[rl0 + 8][0].y + red[rl0 + 8][1].y);
            }
        }
        // fall through to plain store
    }

#pragma unroll
    for (int mt = 0; mt < 2; mt++) {
        const int r0 = row0 + wr * 32 + mt * 16 + lr;
        const int r1 = r0 + 8;
#pragma unroll
        for (int nt = 0; nt < 8; nt++) {
            const int col = wc * 64 + nt * 8 + lc * 2;
            const float d0 = acc[mt][nt][0], d1 = acc[mt][nt][1];
            const float d2 = acc[mt][nt][2], d3 = acc[mt][nt][3];
            if (EPI == 1) {
                if (r0 < rows) {
                    const float keep = (aux1[r0] > 0.f) ? (1.f - kAlpha) : 0.f;
                    const float2 xv = *(const float2*)(aux0 + (size_t)r0 * kD + col);
                    *(float2*)(C + (size_t)r0 * kD + col) =
                        make_float2(keep * d0 + kAlpha * xv.x, keep * d1 + kAlpha * xv.y);
                }
                if (r1 < rows) {
                    const float keep = (aux1[r1] > 0.f) ? (1.f - kAlpha) : 0.f;
                    const float2 xv = *(const float2*)(aux0 + (size_t)r1 * kD + col);
                    *(float2*)(C + (size_t)r1 * kD + col) =
                        make_float2(keep * d2 + kAlpha * xv.x, keep * d3 + kAlpha * xv.y);
                }
            } else {
                if (r0 < rows) *(float2*)(C + (size_t)r0 * kD + col) = make_float2(d0, d1);
                if (r1 < rows) *(float2*)(C + (size_t)r1 * kD + col) = make_float2(d2, d3);
            }
        }
    }
}

template <int EPI>
__global__ __launch_bounds__(256)
void gemm_tf32(const float* __restrict__ A, const float* __restrict__ B,
               const float* __restrict__ bias, const float* __restrict__ aux0,
               const float* __restrict__ aux1, float2* __restrict__ stat,
               float* __restrict__ C, int rows)
{
    gemm_body<EPI>(A, B, bias, aux0, aux1, stat, C, rows, blockIdx.x);
}

// Two GEMMs sharing A: y==0 -> H1 fused LN+ReLU; y==1 -> P (+b2_1) with stats.
__global__ __launch_bounds__(256)
void gemm_dual(const float* __restrict__ A,
               const float* __restrict__ B0, const float* __restrict__ bias0,
               const float* __restrict__ g0, const float* __restrict__ be0,
               float* __restrict__ C0,
               const float* __restrict__ B1, const float* __restrict__ bias1,
               float* __restrict__ C1, int rows)
{
    if (blockIdx.y == 0)
        gemm_body<2>(A, B0, bias0, g0, be0, nullptr, C0, rows, blockIdx.x);
    else
        gemm_body<3>(A, B1, bias1, nullptr, nullptr, g_pstat, C1, rows, blockIdx.x);
}

// W_combo = w1_2 @ W2b (block 0, one 128-row tile), b_combo = b1_2 @ W2b (block 1).
__global__ __launch_bounds__(256)
void combo_kernel(const float* __restrict__ w1_2, const float* __restrict__ W2b,
                  const float* __restrict__ b1_2)
{
    if (blockIdx.x == 0) {
        gemm_body<0>(w1_2, W2b, nullptr, nullptr, nullptr, nullptr, g_Wc, kD, 0);
    } else if (threadIdx.x < kD) {
        const int j = threadIdx.x;
        float s = 0.f;
        for (int k = 0; k < kD; k++) s = fmaf(b1_2[k], W2b[k * kD + j], s);
        g_bc[j] = s;
    }
}

// ---------------------------------------------------------------------------
// Pass 1: warp per edge: Xepre[e] = mean over member vertices of H1.
// ---------------------------------------------------------------------------
__global__ __launch_bounds__(256)
void edge_reduce_kernel()
{
    const int e    = (blockIdx.x * blockDim.x + threadIdx.x) >> 5;
    const int lane = threadIdx.x & 31;
    if (e >= kE) return;
    const int beg = g_eoff[e], end = g_eoff[e + 1];
    float4 acc = make_float4(0.f, 0.f, 0.f, 0.f);
    int j = beg;
    for (; j + 1 < end; j += 2) {
        const int v0 = g_eadj[j];
        const int v1 = g_eadj[j + 1];
        const float4 a = *((const float4*)(g_H1 + (size_t)v0 * kD) + lane);
        const float4 b = *((const float4*)(g_H1 + (size_t)v1 * kD) + lane);
        acc.x += a.x + b.x; acc.y += a.y + b.y;
        acc.z += a.z + b.z; acc.w += a.w + b.w;
    }
    if (j < end) {
        const int v0 = g_eadj[j];
        const float4 a = *((const float4*)(g_H1 + (size_t)v0 * kD) + lane);
        acc.x += a.x; acc.y += a.y; acc.z += a.z; acc.w += a.w;
    }
    const float inv = 1.f / fmaxf((float)(end - beg), 1.f);
    acc.x *= inv; acc.y *= inv; acc.z *= inv; acc.w *= inv;
    *((float4*)(g_Xe + (size_t)e * kD) + lane) = acc;
}

// ---------------------------------------------------------------------------
// Pass 2: warp per vertex. LN stats via precomputed row sums + one dot-reduce:
//   sum(h) = sp[v] + sq[e];  sum(h^2) = qp[v] + 2*dot(P[v],Q[e]) + qq[e].
// ---------------------------------------------------------------------------
__global__ __launch_bounds__(256)
void vertex_pass_kernel(const float* __restrict__ g,
                        const float* __restrict__ be)
{
    const int v    = (blockIdx.x * blockDim.x + threadIdx.x) >> 5;
    const int lane = threadIdx.x & 31;
    if (v >= kN) return;
    const int beg = g_voff[v], end = g_voff[v + 1];
    const int cnt = end - beg;

    const float4 pr = *((const float4*)(g_P + (size_t)v * kD) + lane);
    const float2 ps = g_pstat[v];
    const float4 gg = *((const float4*)g + lane);
    const float4 bt = *((const float4*)be + lane);

    float4 acc = make_float4(0.f, 0.f, 0.f, 0.f);
    for (int j = beg; j < end; j++) {
        const int e = g_vadj[j];
        const float4 q = *((const float4*)(g_Q + (size_t)e * kD) + lane);
        const float2 qs = g_qstat[e];
        float d = pr.x * q.x + pr.y * q.y + pr.z * q.z + pr.w * q.w;
#pragma unroll
        for (int o = 16; o >= 1; o >>= 1)
            d += __shfl_xor_sync(0xffffffffu, d, o);
        const float mu  = (ps.x + qs.x) * (1.f / 128.f);
        const float msq = (ps.y + 2.f * d + qs.y) * (1.f / 128.f);
        const float rstd = rsqrtf(msq - mu * mu + kEps);
        acc.x += fmaxf((pr.x + q.x - mu) * rstd * gg.x + bt.x, 0.f);
        acc.y += fmaxf((pr.y + q.y - mu) * rstd * gg.y + bt.y, 0.f);
        acc.z += fmaxf((pr.z + q.z - mu) * rstd * gg.z + bt.z, 0.f);
        acc.w += fmaxf((pr.w + q.w - mu) * rstd * gg.w + bt.w, 0.f);
    }
    const float inv = 1.f / fmaxf((float)cnt, 1.f);
    acc.x *= inv; acc.y *= inv; acc.z *= inv; acc.w *= inv;
    *((float4*)(g_S + (size_t)v * kD) + lane) = acc;
    if (lane == 0) g_vcntf[v] = (float)cnt;
}

// ---------------------------------------------------------------------------
extern "C" void kernel_launch(void* const* d_in, const int* in_sizes, int n_in,
                              void* d_out, int out_size)
{
    const float* x    = (const float*)d_in[0];
    const float* w1_1 = (const float*)d_in[1];
    const float* b1_1 = (const float*)d_in[2];
    const float* g1   = (const float*)d_in[3];
    const float* be1  = (const float*)d_in[4];
    const float* w1_2 = (const float*)d_in[5];
    const float* b1_2 = (const float*)d_in[6];
    const float* w2_1 = (const float*)d_in[7];
    const float* b2_1 = (const float*)d_in[8];
    const float* g2   = (const float*)d_in[9];
    const float* be2  = (const float*)d_in[10];
    const float* w2_2 = (const float*)d_in[11];
    const float* b2_2 = (const float*)d_in[12];
    const void*  ei   = d_in[13];
    float* out = (float*)d_out;

    float *H1, *P, *S, *Xe, *Q, *Wc, *bc, *vcntf;
    cudaGetSymbolAddress((void**)&H1,    g_H1);
    cudaGetSymbolAddress((void**)&P,     g_P);
    cudaGetSymbolAddress((void**)&S,     g_S);
    cudaGetSymbolAddress((void**)&Xe,    g_Xe);
    cudaGetSymbolAddress((void**)&Q,     g_Q);
    cudaGetSymbolAddress((void**)&Wc,    g_Wc);
    cudaGetSymbolAddress((void**)&bc,    g_bc);
    cudaGetSymbolAddress((void**)&vcntf, g_vcntf);
    float2* qstat;
    cudaGetSymbolAddress((void**)&qstat, g_qstat);

    const int gbN = (kN + 127) / 128;   // 313
    const int gbE = (kE + 127) / 128;   // 157

    // ---- index decode + CSR build ----
    zero_hist_kernel<<<256, 256>>>((const int*)ei);
    decode_kernel<<<(kM + 255) / 256, 256>>>(ei);
    scan1_kernel<<<dim3(kNB_V, 2), 256>>>();
    scan2_kernel<<<1, 64>>>();
    scan3_kernel<<<dim3(kNB_V, 2), 256>>>();
    build_kernel<<<(kM + 255) / 256, 256>>>();

    // ---- W_combo = w1_2 @ W2b, b_combo = b1_2 @ W2b ----
    combo_kernel<<<2, 256>>>(w1_2, w2_1 + kD * kD, b1_2);

    // ---- H1 = relu(LN(x@w1_1+b1_1)), P = x@W2a + b2_1 (+stats) ----
    gemm_dual<<<dim3(gbN, 2), 256>>>(x, w1_1, b1_1, g1, be1, H1,
                                     w2_1, b2_1, P, kN);
    // Xepre[e] = mean of H1 over members
    edge_reduce_kernel<<<(kE * 32 + 255) / 256, 256>>>();
    // Q = Xepre @ W_combo + b_combo (+stats)
    gemm_tf32<3><<<gbE, 256>>>(Xe, Wc, bc, nullptr, nullptr, qstat, Q, kE);
    // S[v] = mean over edges of relu(LN(P[v]+Q[e])); degree -> vcntf
    vertex_pass_kernel<<<(kN * 32 + 255) / 256, 256>>>(g2, be2);
    // out = (1-a)*mask*(S@w2_2 + b2_2) + a*x
    gemm_tf32<1><<<gbN, 256>>>(S, w2_2, b2_2, x, vcntf, nullptr, out, kN);
}

// round 7
// speedup vs baseline: 2.3987x; 1.0900x over previous
#include <cuda_runtime.h>
#include <cstdint>

// ---------------------------------------------------------------------------
// EquivDiffusion: hypergraph two-stage MLP diffusion.
//   H1 = relu(LN(x @ w1_1 + b1_1))            (fused LN epilogue)
//   Xepre[e] = mean_{v in e} H1[v]            (warp-per-edge gather)
//   Q = Xepre @ (w1_2 @ W2b) + (b1_2 @ W2b)   (GEMM composition)
//   P = x @ W2a + b2_1
//   S[v] = mean_{e in v} relu(LN(P[v]+Q[e]))  (warp-per-vertex, stats trick)
//   out = (1-a)*mask(deg>0)*(S @ w2_2 + b2_2) + a*x
// CSR build chain runs on a forked stream, overlapped with the GEMM chain.
// ---------------------------------------------------------------------------

namespace {
constexpr int   kN = 40000;
constexpr int   kE = 20000;
constexpr int   kM = 640000;
constexpr int   kD = 128;
constexpr float kAlpha = 0.1f;
constexpr float kEps   = 1e-5f;
constexpr int   kNB_E = (kE + 1023) / 1024;   // 20
constexpr int   kNB_V = (kN + 1023) / 1024;   // 40
}

__device__ __align__(16) float g_H1[kN * kD];
__device__ __align__(16) float g_P [kN * kD];
__device__ __align__(16) float g_S [kN * kD];
__device__ __align__(16) float g_Xe[kE * kD];   // Xepre
__device__ __align__(16) float g_Q [kE * kD];
__device__ __align__(16) float g_Wc[kD * kD];   // w1_2 @ W2b
__device__ __align__(16) float g_bc[kD];        // b1_2 @ W2b
__device__ __align__(16) float2 g_pstat[kN];    // (sum, sumsq) of P rows
__device__ __align__(16) float2 g_qstat[kE];    // (sum, sumsq) of Q rows
__device__ float g_vcntf[kN];
__device__ int   g_vi[kM], g_ej[kM];
__device__ __align__(16) int g_ecnt[kE];
__device__ __align__(16) int g_vcnt[kN];
__device__ __align__(16) int g_eoff[kE + 4];
__device__ __align__(16) int g_voff[kN + 4];
__device__ int   g_ecur[kE], g_vcur[kN];
__device__ int   g_eadj[kM];     // vertices grouped by edge
__device__ int   g_vadj[kM];     // edges grouped by vertex
__device__ int   g_bsume[64], g_bsumv[64];
__device__ int   g_is64;

// ---------------------------------------------------------------------------
__device__ __forceinline__ uint32_t f2tf32(float f)
{
    uint32_t u;
    asm("cvt.rna.tf32.f32 %0, %1;" : "=r"(u) : "f"(f));
    return u;
}

__device__ __forceinline__ void mma_tf32(float* d, const uint32_t* a, const uint32_t* b)
{
    asm volatile(
        "mma.sync.aligned.m16n8k8.row.col.f32.tf32.tf32.f32 "
        "{%0,%1,%2,%3}, {%4,%5,%6,%7}, {%8,%9}, {%0,%1,%2,%3};"
        : "+f"(d[0]), "+f"(d[1]), "+f"(d[2]), "+f"(d[3])
        : "r"(a[0]), "r"(a[1]), "r"(a[2]), "r"(a[3]), "r"(b[0]), "r"(b[1]));
}

// ---------------------------------------------------------------------------
// zero hists + (block 0) probe int64 vs int32 edge_index.
// ---------------------------------------------------------------------------
__global__ __launch_bounds__(256)
void zero_hist_kernel(const int* __restrict__ ei_as_i32)
{
    const int stride = gridDim.x * blockDim.x;
    const int t = blockIdx.x * blockDim.x + threadIdx.x;
    for (int i = t; i < kE; i += stride) { g_ecnt[i] = 0; g_ecur[i] = 0; }
    for (int i = t; i < kN; i += stride) { g_vcnt[i] = 0; g_vcur[i] = 0; }
    if (blockIdx.x == 0 && threadIdx.x == 0) {
        int all_zero_high = 1;
        for (int k = 0; k < 128; k++) {
            const int idx = k * (kM / 512);          // in-bounds for both layouts
            if (ei_as_i32[2 * idx + 1] != 0) { all_zero_high = 0; break; }
        }
        g_is64 = all_zero_high;
    }
}

__global__ __launch_bounds__(256)
void decode_kernel(const void* __restrict__ ei)
{
    const int t = blockIdx.x * blockDim.x + threadIdx.x;
    if (t >= kM) return;
    int v, e;
    if (g_is64) {
        const long long* p = (const long long*)ei;
        v = (int)p[t];
        e = (int)p[kM + t];
    } else {
        const int* p = (const int*)ei;
        v = p[t];
        e = p[kM + t];
    }
    g_vi[t] = v;
    g_ej[t] = e;
    atomicAdd(&g_ecnt[e], 1);
    atomicAdd(&g_vcnt[v], 1);
}

// ---------------------------------------------------------------------------
// Scan phase 1: per-block (1024 elems) exclusive scan + block sum.
// ---------------------------------------------------------------------------
__global__ __launch_bounds__(256)
void scan1_kernel()
{
    __shared__ int sh[256];
    const int which = blockIdx.y;
    const int n     = which ? kN : kE;
    const int* cnt  = which ? g_vcnt : g_ecnt;
    int* off        = which ? g_voff : g_eoff;
    int* bsum       = which ? g_bsumv : g_bsume;
    const int base  = blockIdx.x * 1024;
    if (base >= n) return;
    const int tid = threadIdx.x;
    const int idx = base + tid * 4;

    int4 a = make_int4(0, 0, 0, 0);
    if (idx < n) a = *(const int4*)(cnt + idx);
    const int t0 = a.x;
    const int t1 = t0 + a.y;
    const int t2 = t1 + a.z;
    const int t3 = t2 + a.w;
    sh[tid] = t3;
    __syncthreads();
#pragma unroll
    for (int o = 1; o < 256; o <<= 1) {
        const int u = (tid >= o) ? sh[tid - o] : 0;
        __syncthreads();
        sh[tid] += u;
        __syncthreads();
    }
    const int prev = sh[tid] - t3;
    if (idx < n) *(int4*)(off + idx) = make_int4(prev, prev + t0, prev + t1, prev + t2);
    if (tid == 255) bsum[blockIdx.x] = sh[255];
}

// ---------------------------------------------------------------------------
// Scan phase 2+3 merged: each block reduces its predecessor block sums
// directly (<=40 values) and adds; block 0 writes the total into off[n].
// ---------------------------------------------------------------------------
__global__ __launch_bounds__(256)
void scan23_kernel()
{
    const int which = blockIdx.y;
    const int n     = which ? kN : kE;
    const int nb    = which ? kNB_V : kNB_E;
    int* off        = which ? g_voff : g_eoff;
    const int* bsum = which ? g_bsumv : g_bsume;
    const int bid   = blockIdx.x;
    if (bid * 1024 >= n) return;

    __shared__ int sadd;
    if (threadIdx.x < 32) {
        const int lim = bid ? bid : nb;      // block 0 sums everything (total)
        int v = 0;
        for (int i = threadIdx.x; i < lim; i += 32) v += bsum[i];
#pragma unroll
        for (int o = 16; o >= 1; o >>= 1) v += __shfl_xor_sync(0xffffffffu, v, o);
        if (threadIdx.x == 0) {
            if (bid == 0) { off[n] = v; sadd = 0; }
            else sadd = v;
        }
    }
    __syncthreads();
    if (bid == 0) return;
    const int add = sadd;
    const int idx = bid * 1024 + threadIdx.x * 4;
    if (idx < n) {
        int4 o = *(int4*)(off + idx);
        o.x += add; o.y += add; o.z += add; o.w += add;
        *(int4*)(off + idx) = o;
    }
}

__global__ __launch_bounds__(256)
void build_kernel()
{
    const int t = blockIdx.x * blockDim.x + threadIdx.x;
    if (t >= kM) return;
    const int v = g_vi[t];
    const int e = g_ej[t];
    const int pe = g_eoff[e] + atomicAdd(&g_ecur[e], 1);
    g_eadj[pe] = v;
    const int pv = g_voff[v] + atomicAdd(&g_vcur[v], 1);
    g_vadj[pv] = e;
}

// ---------------------------------------------------------------------------
// tf32 GEMM body: C[rows,128] = A[rows,128] @ B[128,128] (+bias).
// EPI==0: plain.
// EPI==1: out = keep(row)*acc + alpha*aux0 row (aux1 = count array).
// EPI==2: out = relu(LN(acc)), gamma=aux0, beta=aux1 (full-row LN).
// EPI==3: plain store + per-row (sum, sumsq) written to stat.
// ---------------------------------------------------------------------------
template <int EPI>
__device__ __forceinline__
void gemm_body(const float* __restrict__ A, const float* __restrict__ B,
               const float* __restrict__ bias, const float* __restrict__ aux0,
               const float* __restrict__ aux1, float2* __restrict__ stat,
               float* __restrict__ C, int rows, int tile)
{
    __shared__ uint32_t As[2][128][20];
    __shared__ uint32_t Bs[2][16][136];
    __shared__ float2   red[128][2];

    const int t    = threadIdx.x;
    const int lane = t & 31;
    const int wid  = t >> 5;
    const int wr   = wid & 3;
    const int wc   = wid >> 2;
    const int lr   = lane >> 2;
    const int lc   = lane & 3;
    const int row0 = tile * 128;

    const int arow = row0 + (t >> 1);
    const bool aval = (arow < rows);
    const float* Ap = A + (size_t)arow * kD + (t & 1) * 8;
    const float* Bp = B + (size_t)(t >> 4) * kD + (t & 15) * 8;

    float acc[2][8][4];
#pragma unroll
    for (int mt = 0; mt < 2; mt++)
#pragma unroll
        for (int nt = 0; nt < 8; nt++)
#pragma unroll
            for (int i = 0; i < 4; i++) acc[mt][nt][i] = 0.f;

    float4 pa0 = make_float4(0,0,0,0), pa1 = make_float4(0,0,0,0), pb0, pb1;
    if (aval) { pa0 = *(const float4*)Ap; pa1 = *(const float4*)(Ap + 4); }
    pb0 = *(const float4*)Bp; pb1 = *(const float4*)(Bp + 4);
    {
        uint32_t* as = &As[0][t >> 1][(t & 1) * 8];
        as[0] = f2tf32(pa0.x); as[1] = f2tf32(pa0.y); as[2] = f2tf32(pa0.z); as[3] = f2tf32(pa0.w);
        as[4] = f2tf32(pa1.x); as[5] = f2tf32(pa1.y); as[6] = f2tf32(pa1.z); as[7] = f2tf32(pa1.w);
        uint32_t* bs = &Bs[0][t >> 4][(t & 15) * 8];
        bs[0] = f2tf32(pb0.x); bs[1] = f2tf32(pb0.y); bs[2] = f2tf32(pb0.z); bs[3] = f2tf32(pb0.w);
        bs[4] = f2tf32(pb1.x); bs[5] = f2tf32(pb1.y); bs[6] = f2tf32(pb1.z); bs[7] = f2tf32(pb1.w);
    }
    __syncthreads();

    for (int s = 0; s < 8; s++) {
        const int buf = s & 1;
        if (s < 7) {
            if (aval) {
                const float* ap = Ap + (s + 1) * 16;
                pa0 = *(const float4*)ap; pa1 = *(const float4*)(ap + 4);
            }
            const float* bp = Bp + (size_t)(s + 1) * 16 * kD;
            pb0 = *(const float4*)bp; pb1 = *(const float4*)(bp + 4);
        }
#pragma unroll
        for (int h = 0; h < 2; h++) {
            const int ks = h * 8;
            uint32_t af[2][4];
#pragma unroll
            for (int mt = 0; mt < 2; mt++) {
                const int rb = wr * 32 + mt * 16;
                af[mt][0] = As[buf][rb + lr][ks + lc];
                af[mt][1] = As[buf][rb + lr + 8][ks + lc];
                af[mt][2] = As[buf][rb + lr][ks + lc + 4];
                af[mt][3] = As[buf][rb + lr + 8][ks + lc + 4];
            }
            uint32_t bfr[8][2];
#pragma unroll
            for (int nt = 0; nt < 8; nt++) {
                const int cb = wc * 64 + nt * 8;
                bfr[nt][0] = Bs[buf][ks + lc][cb + lr];
                bfr[nt][1] = Bs[buf][ks + lc + 4][cb + lr];
            }
#pragma unroll
            for (int mt = 0; mt < 2; mt++)
#pragma unroll
                for (int nt = 0; nt < 8; nt++)
                    mma_tf32(acc[mt][nt], af[mt], bfr[nt]);
        }
        if (s < 7) {
            const int nb = buf ^ 1;
            uint32_t* as = &As[nb][t >> 1][(t & 1) * 8];
            as[0] = f2tf32(pa0.x); as[1] = f2tf32(pa0.y); as[2] = f2tf32(pa0.z); as[3] = f2tf32(pa0.w);
            as[4] = f2tf32(pa1.x); as[5] = f2tf32(pa1.y); as[6] = f2tf32(pa1.z); as[7] = f2tf32(pa1.w);
            uint32_t* bs = &Bs[nb][t >> 4][(t & 15) * 8];
            bs[0] = f2tf32(pb0.x); bs[1] = f2tf32(pb0.y); bs[2] = f2tf32(pb0.z); bs[3] = f2tf32(pb0.w);
            bs[4] = f2tf32(pb1.x); bs[5] = f2tf32(pb1.y); bs[6] = f2tf32(pb1.z); bs[7] = f2tf32(pb1.w);
            __syncthreads();
        }
    }

    if (bias != nullptr) {
#pragma unroll
        for (int nt = 0; nt < 8; nt++) {
            const float2 bv = *(const float2*)(bias + wc * 64 + nt * 8 + lc * 2);
#pragma unroll
            for (int mt = 0; mt < 2; mt++) {
                acc[mt][nt][0] += bv.x; acc[mt][nt][1] += bv.y;
                acc[mt][nt][2] += bv.x; acc[mt][nt][3] += bv.y;
            }
        }
    }

    if (EPI == 2 || EPI == 3) {
        float s_[2][2], q_[2][2];
#pragma unroll
        for (int mt = 0; mt < 2; mt++) {
            s_[mt][0] = s_[mt][1] = q_[mt][0] = q_[mt][1] = 0.f;
#pragma unroll
            for (int nt = 0; nt < 8; nt++) {
                s_[mt][0] += acc[mt][nt][0] + acc[mt][nt][1];
                q_[mt][0] += acc[mt][nt][0] * acc[mt][nt][0] + acc[mt][nt][1] * acc[mt][nt][1];
                s_[mt][1] += acc[mt][nt][2] + acc[mt][nt][3];
                q_[mt][1] += acc[mt][nt][2] * acc[mt][nt][2] + acc[mt][nt][3] * acc[mt][nt][3];
            }
        }
#pragma unroll
        for (int o = 1; o <= 2; o <<= 1) {
#pragma unroll
            for (int mt = 0; mt < 2; mt++)
#pragma unroll
                for (int r = 0; r < 2; r++) {
                    s_[mt][r] += __shfl_xor_sync(0xffffffffu, s_[mt][r], o);
                    q_[mt][r] += __shfl_xor_sync(0xffffffffu, q_[mt][r], o);
                }
        }
        if (lc == 0) {
#pragma unroll
            for (int mt = 0; mt < 2; mt++) {
                red[wr * 32 + mt * 16 + lr][wc]     = make_float2(s_[mt][0], q_[mt][0]);
                red[wr * 32 + mt * 16 + lr + 8][wc] = make_float2(s_[mt][1], q_[mt][1]);
            }
        }
        __syncthreads();
    }

    if (EPI == 2) {
#pragma unroll
        for (int mt = 0; mt < 2; mt++) {
            const int rl0 = wr * 32 + mt * 16 + lr;
            const float2 a0 = red[rl0][0],     b0 = red[rl0][1];
            const float2 a1 = red[rl0 + 8][0], b1 = red[rl0 + 8][1];
            const float mu0 = (a0.x + b0.x) * (1.f / 128.f);
            const float mu1 = (a1.x + b1.x) * (1.f / 128.f);
            const float rs0 = rsqrtf((a0.y + b0.y) * (1.f / 128.f) - mu0 * mu0 + kEps);
            const float rs1 = rsqrtf((a1.y + b1.y) * (1.f / 128.f) - mu1 * mu1 + kEps);
            const int r0 = row0 + rl0, r1 = r0 + 8;
#pragma unroll
            for (int nt = 0; nt < 8; nt++) {
                const int col = wc * 64 + nt * 8 + lc * 2;
                const float2 gm = *(const float2*)(aux0 + col);
                const float2 bt = *(const float2*)(aux1 + col);
                if (r0 < rows) {
                    const float v0 = fmaxf((acc[mt][nt][0] - mu0) * rs0 * gm.x + bt.x, 0.f);
                    const float v1 = fmaxf((acc[mt][nt][1] - mu0) * rs0 * gm.y + bt.y, 0.f);
                    *(float2*)(C + (size_t)r0 * kD + col) = make_float2(v0, v1);
                }
                if (r1 < rows) {
                    const float v2 = fmaxf((acc[mt][nt][2] - mu1) * rs1 * gm.x + bt.x, 0.f);
                    const float v3 = fmaxf((acc[mt][nt][3] - mu1) * rs1 * gm.y + bt.y, 0.f);
                    *(float2*)(C + (size_t)r1 * kD + col) = make_float2(v2, v3);
                }
            }
        }
        return;
    }

    if (EPI == 3) {
        if (wc == 0 && lc == 0) {
#pragma unroll
            for (int mt = 0; mt < 2; mt++) {
                const int rl0 = wr * 32 + mt * 16 + lr;
                const int r0 = row0 + rl0;
                if (r0 < rows)
                    stat[r0] = make_float2(red[rl0][0].x + red[rl0][1].x,
                                           red[rl0][0].y + red[rl0][1].y);
                const int r1 = r0 + 8;
                if (r1 < rows)
                    stat[r1] = make_float2(red[rl0 + 8][0].x + red[rl0 + 8][1].x,
                                           red[rl0 + 8][0].y + red[rl0 + 8][1].y);
            }
        }
    }

#pragma unroll
    for (int mt = 0; mt < 2; mt++) {
        const int r0 = row0 + wr * 32 + mt * 16 + lr;
        const int r1 = r0 + 8;
#pragma unroll
        for (int nt = 0; nt < 8; nt++) {
            const int col = wc * 64 + nt * 8 + lc * 2;
            const float d0 = acc[mt][nt][0], d1 = acc[mt][nt][1];
            const float d2 = acc[mt][nt][2], d3 = acc[mt][nt][3];
            if (EPI == 1) {
                if (r0 < rows) {
                    const float keep = (aux1[r0] > 0.f) ? (1.f - kAlpha) : 0.f;
                    const float2 xv = *(const float2*)(aux0 + (size_t)r0 * kD + col);
                    *(float2*)(C + (size_t)r0 * kD + col) =
                        make_float2(keep * d0 + kAlpha * xv.x, keep * d1 + kAlpha * xv.y);
                }
                if (r1 < rows) {
                    const float keep = (aux1[r1] > 0.f) ? (1.f - kAlpha) : 0.f;
                    const float2 xv = *(const float2*)(aux0 + (size_t)r1 * kD + col);
                    *(float2*)(C + (size_t)r1 * kD + col) =
                        make_float2(keep * d2 + kAlpha * xv.x, keep * d3 + kAlpha * xv.y);
                }
            } else {
                if (r0 < rows) *(float2*)(C + (size_t)r0 * kD + col) = make_float2(d0, d1);
                if (r1 < rows) *(float2*)(C + (size_t)r1 * kD + col) = make_float2(d2, d3);
            }
        }
    }
}

template <int EPI>
__global__ __launch_bounds__(256)
void gemm_tf32(const float* __restrict__ A, const float* __restrict__ B,
               const float* __restrict__ bias, const float* __restrict__ aux0,
               const float* __restrict__ aux1, float2* __restrict__ stat,
               float* __restrict__ C, int rows)
{
    gemm_body<EPI>(A, B, bias, aux0, aux1, stat, C, rows, blockIdx.x);
}

// Two GEMMs sharing A: y==0 -> H1 fused LN+ReLU; y==1 -> P (+b2_1) with stats.
__global__ __launch_bounds__(256)
void gemm_dual(const float* __restrict__ A,
               const float* __restrict__ B0, const float* __restrict__ bias0,
               const float* __restrict__ g0, const float* __restrict__ be0,
               float* __restrict__ C0,
               const float* __restrict__ B1, const float* __restrict__ bias1,
               float* __restrict__ C1, int rows)
{
    if (blockIdx.y == 0)
        gemm_body<2>(A, B0, bias0, g0, be0, nullptr, C0, rows, blockIdx.x);
    else
        gemm_body<3>(A, B1, bias1, nullptr, nullptr, g_pstat, C1, rows, blockIdx.x);
}

// W_combo = w1_2 @ W2b (block 0), b_combo = b1_2 @ W2b (block 1).
__global__ __launch_bounds__(256)
void combo_kernel(const float* __restrict__ w1_2, const float* __restrict__ W2b,
                  const float* __restrict__ b1_2)
{
    if (blockIdx.x == 0) {
        gemm_body<0>(w1_2, W2b, nullptr, nullptr, nullptr, nullptr, g_Wc, kD, 0);
    } else if (threadIdx.x < kD) {
        const int j = threadIdx.x;
        float s = 0.f;
        for (int k = 0; k < kD; k++) s = fmaf(b1_2[k], W2b[k * kD + j], s);
        g_bc[j] = s;
    }
}

// ---------------------------------------------------------------------------
// Pass 1: warp per edge: Xepre[e] = mean over member vertices of H1.
// ---------------------------------------------------------------------------
__global__ __launch_bounds__(256)
void edge_reduce_kernel()
{
    const int e    = (blockIdx.x * blockDim.x + threadIdx.x) >> 5;
    const int lane = threadIdx.x & 31;
    if (e >= kE) return;
    const int beg = g_eoff[e], end = g_eoff[e + 1];
    float4 acc = make_float4(0.f, 0.f, 0.f, 0.f);
    int j = beg;
    for (; j + 1 < end; j += 2) {
        const int v0 = g_eadj[j];
        const int v1 = g_eadj[j + 1];
        const float4 a = *((const float4*)(g_H1 + (size_t)v0 * kD) + lane);
        const float4 b = *((const float4*)(g_H1 + (size_t)v1 * kD) + lane);
        acc.x += a.x + b.x; acc.y += a.y + b.y;
        acc.z += a.z + b.z; acc.w += a.w + b.w;
    }
    if (j < end) {
        const int v0 = g_eadj[j];
        const float4 a = *((const float4*)(g_H1 + (size_t)v0 * kD) + lane);
        acc.x += a.x; acc.y += a.y; acc.z += a.z; acc.w += a.w;
    }
    const float inv = 1.f / fmaxf((float)(end - beg), 1.f);
    acc.x *= inv; acc.y *= inv; acc.z *= inv; acc.w *= inv;
    *((float4*)(g_Xe + (size_t)e * kD) + lane) = acc;
}

// ---------------------------------------------------------------------------
// Pass 2: warp per vertex, LN stats via precomputed row sums + one dot-reduce.
// ---------------------------------------------------------------------------
__global__ __launch_bounds__(256)
void vertex_pass_kernel(const float* __restrict__ g,
                        const float* __restrict__ be)
{
    const int v    = (blockIdx.x * blockDim.x + threadIdx.x) >> 5;
    const int lane = threadIdx.x & 31;
    if (v >= kN) return;
    const int beg = g_voff[v], end = g_voff[v + 1];
    const int cnt = end - beg;

    const float4 pr = *((const float4*)(g_P + (size_t)v * kD) + lane);
    const float2 ps = g_pstat[v];
    const float4 gg = *((const float4*)g + lane);
    const float4 bt = *((const float4*)be + lane);

    float4 acc = make_float4(0.f, 0.f, 0.f, 0.f);
    for (int j = beg; j < end; j++) {
        const int e = g_vadj[j];
        const float4 q = *((const float4*)(g_Q + (size_t)e * kD) + lane);
        const float2 qs = g_qstat[e];
        float d = pr.x * q.x + pr.y * q.y + pr.z * q.z + pr.w * q.w;
#pragma unroll
        for (int o = 16; o >= 1; o >>= 1)
            d += __shfl_xor_sync(0xffffffffu, d, o);
        const float mu  = (ps.x + qs.x) * (1.f / 128.f);
        const float msq = (ps.y + 2.f * d + qs.y) * (1.f / 128.f);
        const float rstd = rsqrtf(msq - mu * mu + kEps);
        acc.x += fmaxf((pr.x + q.x - mu) * rstd * gg.x + bt.x, 0.f);
        acc.y += fmaxf((pr.y + q.y - mu) * rstd * gg.y + bt.y, 0.f);
        acc.z += fmaxf((pr.z + q.z - mu) * rstd * gg.z + bt.z, 0.f);
        acc.w += fmaxf((pr.w + q.w - mu) * rstd * gg.w + bt.w, 0.f);
    }
    const float inv = 1.f / fmaxf((float)cnt, 1.f);
    acc.x *= inv; acc.y *= inv; acc.z *= inv; acc.w *= inv;
    *((float4*)(g_S + (size_t)v * kD) + lane) = acc;
    if (lane == 0) g_vcntf[v] = (float)cnt;
}

// ---------------------------------------------------------------------------
extern "C" void kernel_launch(void* const* d_in, const int* in_sizes, int n_in,
                              void* d_out, int out_size)
{
    const float* x    = (const float*)d_in[0];
    const float* w1_1 = (const float*)d_in[1];
    const float* b1_1 = (const float*)d_in[2];
    const float* g1   = (const float*)d_in[3];
    const float* be1  = (const float*)d_in[4];
    const float* w1_2 = (const float*)d_in[5];
    const float* b1_2 = (const float*)d_in[6];
    const float* w2_1 = (const float*)d_in[7];
    const float* b2_1 = (const float*)d_in[8];
    const float* g2   = (const float*)d_in[9];
    const float* be2  = (const float*)d_in[10];
    const float* w2_2 = (const float*)d_in[11];
    const float* b2_2 = (const float*)d_in[12];
    const void*  ei   = d_in[13];
    float* out = (float*)d_out;

    float *H1, *P, *S, *Xe, *Q, *Wc, *bc, *vcntf;
    cudaGetSymbolAddress((void**)&H1,    g_H1);
    cudaGetSymbolAddress((void**)&P,     g_P);
    cudaGetSymbolAddress((void**)&S,     g_S);
    cudaGetSymbolAddress((void**)&Xe,    g_Xe);
    cudaGetSymbolAddress((void**)&Q,     g_Q);
    cudaGetSymbolAddress((void**)&Wc,    g_Wc);
    cudaGetSymbolAddress((void**)&bc,    g_bc);
    cudaGetSymbolAddress((void**)&vcntf, g_vcntf);
    float2* qstat;
    cudaGetSymbolAddress((void**)&qstat, g_qstat);

    // Side stream + fork/join events: created once on the first
    // (non-capturing, correctness) call; reused during graph capture.
    static cudaStream_t sB = nullptr;
    static cudaEvent_t evFork = nullptr, evJoin = nullptr;
    if (sB == nullptr) {
        cudaStreamCreateWithFlags(&sB, cudaStreamNonBlocking);
        cudaEventCreateWithFlags(&evFork, cudaEventDisableTiming);
        cudaEventCreateWithFlags(&evJoin, cudaEventDisableTiming);
    }

    const int gbN = (kN + 127) / 128;   // 313
    const int gbE = (kE + 127) / 128;   // 157

    // ---- fork: CSR build + combo on side stream ----
    cudaEventRecord(evFork, 0);
    cudaStreamWaitEvent(sB, evFork, 0);

    combo_kernel<<<2, 256, 0, sB>>>(w1_2, w2_1 + kD * kD, b1_2);
    zero_hist_kernel<<<256, 256, 0, sB>>>((const int*)ei);
    decode_kernel<<<(kM + 255) / 256, 256, 0, sB>>>(ei);
    scan1_kernel<<<dim3(kNB_V, 2), 256, 0, sB>>>();
    scan23_kernel<<<dim3(kNB_V, 2), 256, 0, sB>>>();
    build_kernel<<<(kM + 255) / 256, 256, 0, sB>>>();
    cudaEventRecord(evJoin, sB);

    // ---- main stream: H1 = relu(LN(x@w1_1+b1_1)), P = x@W2a + b2_1 ----
    gemm_dual<<<dim3(gbN, 2), 256>>>(x, w1_1, b1_1, g1, be1, H1,
                                     w2_1, b2_1, P, kN);

    // ---- join, then the serial tail ----
    cudaStreamWaitEvent(0, evJoin, 0);
    edge_reduce_kernel<<<(kE * 32 + 255) / 256, 256>>>();
    gemm_tf32<3><<<gbE, 256>>>(Xe, Wc, bc, nullptr, nullptr, qstat, Q, kE);
    vertex_pass_kernel<<<(kN * 32 + 255) / 256, 256>>>(g2, be2);
    gemm_tf32<1><<<gbN, 256>>>(S, w2_2, b2_2, x, vcntf, nullptr, out, kN);
}